// round 1
// baseline (speedup 1.0000x reference)
#include <cuda_runtime.h>
#include <math.h>

#define BATCH 4
#define D 64
#define Himg 256
#define Wimg 256
#define Npix 65536
#define OC 192
#define HEADS 8

// Scratch (device globals — allocation-free per harness rules)
__device__ float g_pw[(size_t)8 * OC * Npix];   // pw conv output, [b*2+br][192][N]
__device__ float g_v[(size_t)8 * D * Npix];     // v after dw,   [b*2+br][64][N]
__device__ float g_sq[8 * 128];                 // sumsq q(64)+k(64) per (b,br)
__device__ float g_gram[8 * 64 * 8];            // Gram [c][j] per (b,br)
__device__ float g_M[8 * 64 * 64];              // folded (w_po @ attn) per (b,br)

__device__ __forceinline__ unsigned long long pack2(float x, float y) {
    unsigned long long u;
    asm("mov.b64 %0, {%1, %2};" : "=l"(u) : "f"(x), "f"(y));
    return u;
}
__device__ __forceinline__ unsigned long long ffma2(unsigned long long a,
                                                    unsigned long long b,
                                                    unsigned long long c) {
    unsigned long long d;
    asm("fma.rn.f32x2 %0, %1, %2, %3;" : "=l"(d) : "l"(a), "l"(b), "l"(c));
    return d;
}

// ---------------- K0: zero the reduction accumulators ----------------
__global__ void k0_zero() {
    int i = blockIdx.x * blockDim.x + threadIdx.x;
    if (i < 8 * 128) g_sq[i] = 0.f;
    if (i < 8 * 64 * 8) g_gram[i] = 0.f;
}

// ---------------- K1: pointwise conv (192x64 GEMM), f32x2 packed ----------------
// grid (128, 8), block 256. Each thread: 2 pixels. Weights staged as {w,w} pairs
// in smem in two 96-channel phases (keeps static smem <= 48KB).
__global__ __launch_bounds__(256) void k1_pw(const float* __restrict__ x,
                                             const float* __restrict__ wq1,
                                             const float* __restrict__ wq2) {
    __shared__ unsigned long long s_w2[96 * 64];
    int bb = blockIdx.y, b = bb >> 1, br = bb & 1;
    const float* wq = br ? wq2 : wq1;
    int tid = threadIdx.x;
    int p0 = (blockIdx.x * 256 + tid) * 2;
    const float* xb = x + ((size_t)(b * 128 + br * 64)) * Npix + p0;

    unsigned long long xr[64];
#pragma unroll
    for (int c = 0; c < 64; c++)
        xr[c] = *(const unsigned long long*)(xb + (size_t)c * Npix);

    float* outp = g_pw + (size_t)bb * OC * Npix + p0;

    for (int ph = 0; ph < 2; ph++) {
        __syncthreads();
        for (int i = tid; i < 96 * 64; i += 256) {
            float wv = wq[ph * 96 * 64 + i];
            s_w2[i] = pack2(wv, wv);
        }
        __syncthreads();
#pragma unroll 1
        for (int og = 0; og < 96; og += 4) {
            unsigned long long a0 = 0, a1 = 0, a2 = 0, a3 = 0;
            const unsigned long long* wrow = s_w2 + og * 64;
#pragma unroll
            for (int c = 0; c < 64; c++) {
                unsigned long long xv = xr[c];
                a0 = ffma2(wrow[c], xv, a0);
                a1 = ffma2(wrow[64 + c], xv, a1);
                a2 = ffma2(wrow[128 + c], xv, a2);
                a3 = ffma2(wrow[192 + c], xv, a3);
            }
            int oc = ph * 96 + og;
            *(unsigned long long*)(outp + (size_t)(oc + 0) * Npix) = a0;
            *(unsigned long long*)(outp + (size_t)(oc + 1) * Npix) = a1;
            *(unsigned long long*)(outp + (size_t)(oc + 2) * Npix) = a2;
            *(unsigned long long*)(outp + (size_t)(oc + 3) * Npix) = a3;
        }
    }
}

// ---------------- K2: depthwise 3x3 + Gram/sumsq reductions + v store ----------------
// grid (8, 32, 8): 32x8 pixel tiles. smem-staged pw tiles (16 channels at a time)
// to stay off the LDG issue floor.
#define TW2 32
#define TH2 8
#define TSW 34
#define TSN 340  // 34*10
#define TSP 344

__global__ __launch_bounds__(256) void k2_dw(const float* __restrict__ wd1,
                                             const float* __restrict__ wd2) {
    __shared__ float ts[16][TSP];
    __shared__ float qs[8][257];
    __shared__ float ks[8][257];
    __shared__ float wd[OC * 9];

    int bb = blockIdx.z;
    int br = bb & 1;
    const float* wdg = br ? wd2 : wd1;
    int tid = threadIdx.x;
    for (int i = tid; i < OC * 9; i += 256) wd[i] = wdg[i];

    int px = tid & 31, py = tid >> 5;
    int w0 = blockIdx.x * TW2, h0 = blockIdx.y * TH2;
    int w = w0 + px, h = h0 + py;
    const float* pwb = g_pw + (size_t)bb * OC * Npix;
    float* vbp = g_v + (size_t)bb * D * Npix;
    float* outg = g_gram + bb * 512;
    float* outs = g_sq + bb * 128;
    __syncthreads();

    // stage one channel (global channel gc) into ts[ch]
    auto stage_one = [&](int ch, int gc, int idx) {
        int wi = idx;
        int r = wi / TSW, cc = wi % TSW;
        int gh = h0 + r - 1, gw = w0 + cc - 1;
        float v = 0.f;
        if ((unsigned)gh < Himg && (unsigned)gw < Wimg)
            v = pwb[(size_t)gc * Npix + gh * Wimg + gw];
        ts[ch][wi] = v;
    };
    auto dwcalc = [&](int ch, int gc) -> float {
        const float* wk = wd + gc * 9;
        const float* t0 = ts[ch] + py * TSW + px;
        float a = 0.f;
#pragma unroll
        for (int kh = 0; kh < 3; kh++)
#pragma unroll
            for (int kw = 0; kw < 3; kw++)
                a = fmaf(wk[kh * 3 + kw], t0[kh * TSW + kw], a);
        return a;
    };

    // q/k per head: stage 8 q channels + 8 k channels, dw, then Gram + sumsq
    for (int hd = 0; hd < 8; hd++) {
        for (int idx = tid; idx < 16 * TSN; idx += 256) {
            int ch = idx / TSN, wi = idx % TSN;
            int gc = (ch < 8) ? (hd * 8 + ch) : (64 + hd * 8 + (ch - 8));
            stage_one(ch, gc, wi);
        }
        __syncthreads();
#pragma unroll
        for (int i = 0; i < 8; i++) {
            qs[i][tid] = dwcalc(i, hd * 8 + i);
            ks[i][tid] = dwcalc(8 + i, 64 + hd * 8 + i);
        }
        __syncthreads();
        {
            int pair = tid & 63, seg = tid >> 6;
            int qi = pair >> 3, kj = pair & 7;
            const float* qr = qs[qi];
            const float* kr = ks[kj];
            float s = 0.f;
#pragma unroll 8
            for (int p = seg * 64; p < seg * 64 + 64; p++)
                s = fmaf(qr[p], kr[p], s);
            atomicAdd(outg + hd * 64 + pair, s);
        }
        if (tid < 64) {
            int row = tid >> 2, sg = tid & 3;
            const float* r = (row < 8) ? qs[row] : ks[row - 8];
            float s = 0.f;
#pragma unroll 8
            for (int p = sg * 64; p < sg * 64 + 64; p++)
                s = fmaf(r[p], r[p], s);
            int c = (row < 8) ? (hd * 8 + row) : (64 + hd * 8 + (row - 8));
            atomicAdd(outs + c, s);
        }
        __syncthreads();
    }

    // v channels: 4 chunks of 16
    for (int vg = 0; vg < 4; vg++) {
        int c0 = 128 + vg * 16;
        for (int idx = tid; idx < 16 * TSN; idx += 256) {
            int ch = idx / TSN, wi = idx % TSN;
            stage_one(ch, c0 + ch, wi);
        }
        __syncthreads();
#pragma unroll
        for (int i = 0; i < 16; i++) {
            float v = dwcalc(i, c0 + i);
            vbp[(size_t)(c0 - 128 + i) * Npix + h * Wimg + w] = v;
        }
        __syncthreads();
    }
}

// ---------------- K3: attn softmax + fold with w_po into M (tiny) ----------------
__global__ void k3_attn(const float* __restrict__ wpo1, const float* __restrict__ wpo2,
                        const float* __restrict__ t1, const float* __restrict__ t2) {
    int bb = blockIdx.x;
    int br = bb & 1;
    __shared__ float attn[64][9];
    __shared__ float qn[64], kn[64];
    int t = threadIdx.x;
    if (t < 64) {
        qn[t] = fmaxf(sqrtf(g_sq[bb * 128 + t]), 1e-12f);
        kn[t] = fmaxf(sqrtf(g_sq[bb * 128 + 64 + t]), 1e-12f);
    }
    __syncthreads();
    const float* tv = br ? t2 : t1;
    if (t < 64) {
        int hh = t >> 3;
        float tt = tv[hh];
        float s[8], m = -1e30f;
#pragma unroll
        for (int j = 0; j < 8; j++) {
            s[j] = g_gram[bb * 512 + t * 8 + j] / (qn[t] * kn[hh * 8 + j]) * tt;
            m = fmaxf(m, s[j]);
        }
        float sum = 0.f;
#pragma unroll
        for (int j = 0; j < 8; j++) { s[j] = expf(s[j] - m); sum += s[j]; }
        float inv = 1.f / sum;
#pragma unroll
        for (int j = 0; j < 8; j++) attn[t][j] = s[j] * inv;
    }
    __syncthreads();
    const float* wpo = br ? wpo2 : wpo1;
    if (t < 64) {
        for (int d = 0; d < 64; d++) {
            int hd = d >> 3;
            float acc = 0.f;
#pragma unroll
            for (int ci = 0; ci < 8; ci++)
                acc = fmaf(wpo[t * 64 + hd * 8 + ci], attn[hd * 8 + ci][d & 7], acc);
            g_M[bb * 4096 + t * 64 + d] = acc;
        }
    }
}

// ---------------- K4: out = M @ v_other (cross-branch), f32x2 packed ----------------
__global__ __launch_bounds__(256) void k4_out(float* __restrict__ out) {
    __shared__ unsigned long long m2[64 * 64];
    int bh = blockIdx.y;
    int b = bh >> 1, half = bh & 1;
    int mi = b * 2 + half;
    int vi = b * 2 + (1 - half);
    for (int i = threadIdx.x; i < 4096; i += 256) {
        float wv = g_M[mi * 4096 + i];
        m2[i] = pack2(wv, wv);
    }
    __syncthreads();
    int p0 = (blockIdx.x * 256 + threadIdx.x) * 2;
    const float* vp = g_v + (size_t)vi * D * Npix + p0;
    unsigned long long vr[64];
#pragma unroll
    for (int d = 0; d < 64; d++)
        vr[d] = *(const unsigned long long*)(vp + (size_t)d * Npix);
    float* op = out + ((size_t)(b * 128 + half * 64)) * Npix + p0;
#pragma unroll 1
    for (int og = 0; og < 64; og += 4) {
        unsigned long long a0 = 0, a1 = 0, a2 = 0, a3 = 0;
        const unsigned long long* m0 = m2 + og * 64;
#pragma unroll
        for (int d = 0; d < 64; d++) {
            unsigned long long vv = vr[d];
            a0 = ffma2(m0[d], vv, a0);
            a1 = ffma2(m0[64 + d], vv, a1);
            a2 = ffma2(m0[128 + d], vv, a2);
            a3 = ffma2(m0[192 + d], vv, a3);
        }
        *(unsigned long long*)(op + (size_t)(og + 0) * Npix) = a0;
        *(unsigned long long*)(op + (size_t)(og + 1) * Npix) = a1;
        *(unsigned long long*)(op + (size_t)(og + 2) * Npix) = a2;
        *(unsigned long long*)(op + (size_t)(og + 3) * Npix) = a3;
    }
}

extern "C" void kernel_launch(void* const* d_in, const int* in_sizes, int n_in,
                              void* d_out, int out_size) {
    const float* x   = (const float*)d_in[0];
    const float* wq1 = (const float*)d_in[1];
    const float* wq2 = (const float*)d_in[2];
    const float* wd1 = (const float*)d_in[3];
    const float* wd2 = (const float*)d_in[4];
    const float* wp1 = (const float*)d_in[5];
    const float* wp2 = (const float*)d_in[6];
    const float* t1  = (const float*)d_in[7];
    const float* t2  = (const float*)d_in[8];
    float* out = (float*)d_out;

    k0_zero<<<16, 256>>>();
    k1_pw<<<dim3(128, 8), 256>>>(x, wq1, wq2);
    k2_dw<<<dim3(8, 32, 8), 256>>>(wd1, wd2);
    k3_attn<<<8, 64>>>(wp1, wp2, t1, t2);
    k4_out<<<dim3(128, 8), 256>>>(out);
}

// round 2
// speedup vs baseline: 1.0526x; 1.0526x over previous
#include <cuda_runtime.h>
#include <math.h>

#define BATCH 4
#define D 64
#define Himg 256
#define Wimg 256
#define Npix 65536
#define OC 192
#define HEADS 8

// Scratch (device globals — allocation-free per harness rules)
__device__ float g_pw[(size_t)8 * OC * Npix];   // pw conv output, [b*2+br][192][N]
__device__ float g_v[(size_t)8 * D * Npix];     // v after dw,   [b*2+br][64][N]
__device__ float g_sq[8 * 128];                 // sumsq q(64)+k(64) per (b,br)
__device__ float g_gram[8 * 64 * 8];            // Gram [c][j] per (b,br)
__device__ float g_M[8 * 64 * 64];              // folded (w_po @ attn) per (b,br)

__device__ __forceinline__ unsigned long long pack2(float x, float y) {
    unsigned long long u;
    asm("mov.b64 %0, {%1, %2};" : "=l"(u) : "f"(x), "f"(y));
    return u;
}
__device__ __forceinline__ unsigned long long ffma2(unsigned long long a,
                                                    unsigned long long b,
                                                    unsigned long long c) {
    unsigned long long d;
    asm("fma.rn.f32x2 %0, %1, %2, %3;" : "=l"(d) : "l"(a), "l"(b), "l"(c));
    return d;
}

// ---------------- K0: zero the reduction accumulators ----------------
__global__ void k0_zero() {
    int i = blockIdx.x * blockDim.x + threadIdx.x;
    if (i < 8 * 128) g_sq[i] = 0.f;
    if (i < 8 * 64 * 8) g_gram[i] = 0.f;
}

// ---------------- K1: pointwise conv as register-tiled GEMM ----------------
// C[192 x 65536] = W[192x64] @ X[64x65536] per (b,branch).
// Block tile: 64 oc x 512 px, thread tile: 8 oc x 16 px (8 f32x2 accums x 8).
// K staged in smem chunks of 16 rows. Grid.x = oc-tile fastest for L2 reuse of X.
#define PXT 512
#define PXU 256   // u64 columns per tile
#define KC 16

__global__ __launch_bounds__(256) void k1_pw(const float* __restrict__ x,
                                             const float* __restrict__ wq1,
                                             const float* __restrict__ wq2) {
    __shared__ float sW[64 * 64];                  // 16KB
    __shared__ unsigned long long sX[KC * PXU];    // 32KB

    int bx = blockIdx.x;
    int oct = bx % 3, pxt = bx / 3;   // oc-tile fastest -> 3 tiles share X via L2
    int bb = blockIdx.y, b = bb >> 1, br = bb & 1;
    const float* wq = br ? wq2 : wq1;
    int tid = threadIdx.x, lane = tid & 31, wp = tid >> 5;

    for (int i = tid; i < 4096; i += 256) sW[i] = wq[oct * 4096 + i];

    const float* xb = x + ((size_t)(b * 128 + br * 64)) * Npix + pxt * PXT;
    float* outb = g_pw + (size_t)bb * OC * Npix + (size_t)(oct * 64) * Npix + pxt * PXT;

    unsigned long long acc[8][8];
#pragma unroll
    for (int r = 0; r < 8; r++)
#pragma unroll
        for (int j = 0; j < 8; j++) acc[r][j] = 0ull;

    for (int kc = 0; kc < 64; kc += KC) {
        __syncthreads();
#pragma unroll
        for (int r = 0; r < KC; r++)
            sX[r * PXU + tid] =
                *(const unsigned long long*)(xb + (size_t)(kc + r) * Npix + tid * 2);
        __syncthreads();
#pragma unroll
        for (int k = 0; k < KC; k++) {
            unsigned long long xv[8];
#pragma unroll
            for (int j = 0; j < 8; j++) xv[j] = sX[k * PXU + lane + 32 * j];
#pragma unroll
            for (int r = 0; r < 8; r++) {
                float wv = sW[(wp * 8 + r) * 64 + kc + k];
                unsigned long long w2 = pack2(wv, wv);
#pragma unroll
                for (int j = 0; j < 8; j++) acc[r][j] = ffma2(w2, xv[j], acc[r][j]);
            }
        }
    }
#pragma unroll
    for (int r = 0; r < 8; r++) {
        float* orow = outb + (size_t)(wp * 8 + r) * Npix;
#pragma unroll
        for (int j = 0; j < 8; j++)
            *(unsigned long long*)(orow + (lane + 32 * j) * 2) = acc[r][j];
    }
}

// ---------------- K2: depthwise 3x3 + Gram/sumsq reductions + v store ----------------
#define TW2 32
#define TH2 8
#define TSW 34
#define TSN 340  // 34*10
#define TSP 344

__global__ __launch_bounds__(256) void k2_dw(const float* __restrict__ wd1,
                                             const float* __restrict__ wd2) {
    __shared__ float ts[16][TSP];
    __shared__ float qs[8][257];
    __shared__ float ks[8][257];
    __shared__ float wd[OC * 9];

    int bb = blockIdx.z;
    int br = bb & 1;
    const float* wdg = br ? wd2 : wd1;
    int tid = threadIdx.x;
    for (int i = tid; i < OC * 9; i += 256) wd[i] = wdg[i];

    int px = tid & 31, py = tid >> 5;
    int w0 = blockIdx.x * TW2, h0 = blockIdx.y * TH2;
    int w = w0 + px, h = h0 + py;
    const float* pwb = g_pw + (size_t)bb * OC * Npix;
    float* vbp = g_v + (size_t)bb * D * Npix;
    float* outg = g_gram + bb * 512;
    float* outs = g_sq + bb * 128;
    __syncthreads();

    auto stage_one = [&](int ch, int gc, int idx) {
        int wi = idx;
        int r = wi / TSW, cc = wi % TSW;
        int gh = h0 + r - 1, gw = w0 + cc - 1;
        float v = 0.f;
        if ((unsigned)gh < Himg && (unsigned)gw < Wimg)
            v = pwb[(size_t)gc * Npix + gh * Wimg + gw];
        ts[ch][wi] = v;
    };
    auto dwcalc = [&](int ch, int gc) -> float {
        const float* wk = wd + gc * 9;
        const float* t0 = ts[ch] + py * TSW + px;
        float a = 0.f;
#pragma unroll
        for (int kh = 0; kh < 3; kh++)
#pragma unroll
            for (int kw = 0; kw < 3; kw++)
                a = fmaf(wk[kh * 3 + kw], t0[kh * TSW + kw], a);
        return a;
    };

    for (int hd = 0; hd < 8; hd++) {
        for (int idx = tid; idx < 16 * TSN; idx += 256) {
            int ch = idx / TSN, wi = idx % TSN;
            int gc = (ch < 8) ? (hd * 8 + ch) : (64 + hd * 8 + (ch - 8));
            stage_one(ch, gc, wi);
        }
        __syncthreads();
#pragma unroll
        for (int i = 0; i < 8; i++) {
            qs[i][tid] = dwcalc(i, hd * 8 + i);
            ks[i][tid] = dwcalc(8 + i, 64 + hd * 8 + i);
        }
        __syncthreads();
        {
            int pair = tid & 63, seg = tid >> 6;
            int qi = pair >> 3, kj = pair & 7;
            const float* qr = qs[qi];
            const float* kr = ks[kj];
            float s = 0.f;
#pragma unroll 8
            for (int p = seg * 64; p < seg * 64 + 64; p++)
                s = fmaf(qr[p], kr[p], s);
            atomicAdd(outg + hd * 64 + pair, s);
        }
        if (tid < 64) {
            int row = tid >> 2, sg = tid & 3;
            const float* r = (row < 8) ? qs[row] : ks[row - 8];
            float s = 0.f;
#pragma unroll 8
            for (int p = sg * 64; p < sg * 64 + 64; p++)
                s = fmaf(r[p], r[p], s);
            int c = (row < 8) ? (hd * 8 + row) : (64 + hd * 8 + (row - 8));
            atomicAdd(outs + c, s);
        }
        __syncthreads();
    }

    for (int vg = 0; vg < 4; vg++) {
        int c0 = 128 + vg * 16;
        for (int idx = tid; idx < 16 * TSN; idx += 256) {
            int ch = idx / TSN, wi = idx % TSN;
            stage_one(ch, c0 + ch, wi);
        }
        __syncthreads();
#pragma unroll
        for (int i = 0; i < 16; i++) {
            float v = dwcalc(i, c0 + i);
            vbp[(size_t)(c0 - 128 + i) * Npix + h * Wimg + w] = v;
        }
        __syncthreads();
    }
}

// ---------------- K3: attn softmax + fold with w_po into M ----------------
__global__ __launch_bounds__(256) void k3_attn(const float* __restrict__ wpo1,
                                               const float* __restrict__ wpo2,
                                               const float* __restrict__ t1,
                                               const float* __restrict__ t2) {
    int bb = blockIdx.x;
    int br = bb & 1;
    __shared__ float attn[64][9];
    __shared__ float qn[64], kn[64];
    __shared__ float swpo[4096];
    int t = threadIdx.x;
    const float* wpo = br ? wpo2 : wpo1;
    for (int i = t; i < 4096; i += 256) swpo[i] = wpo[i];
    if (t < 64) {
        qn[t] = fmaxf(sqrtf(g_sq[bb * 128 + t]), 1e-12f);
        kn[t] = fmaxf(sqrtf(g_sq[bb * 128 + 64 + t]), 1e-12f);
    }
    __syncthreads();
    const float* tv = br ? t2 : t1;
    if (t < 64) {
        int hh = t >> 3;
        float tt = tv[hh];
        float s[8], m = -1e30f;
#pragma unroll
        for (int j = 0; j < 8; j++) {
            s[j] = g_gram[bb * 512 + t * 8 + j] / (qn[t] * kn[hh * 8 + j]) * tt;
            m = fmaxf(m, s[j]);
        }
        float sum = 0.f;
#pragma unroll
        for (int j = 0; j < 8; j++) { s[j] = expf(s[j] - m); sum += s[j]; }
        float inv = 1.f / sum;
#pragma unroll
        for (int j = 0; j < 8; j++) attn[t][j] = s[j] * inv;
    }
    __syncthreads();
    {
        int o = t >> 2, dg = t & 3;
#pragma unroll
        for (int dd = 0; dd < 16; dd++) {
            int d = dg * 16 + dd;
            int hd = d >> 3;
            float acc = 0.f;
#pragma unroll
            for (int ci = 0; ci < 8; ci++)
                acc = fmaf(swpo[o * 64 + hd * 8 + ci], attn[hd * 8 + ci][d & 7], acc);
            g_M[bb * 4096 + o * 64 + d] = acc;
        }
    }
}

// ---------------- K4: out = M @ v_other, register-tiled GEMM ----------------
// Same structure as K1 but M=64 (single oc tile), W = folded g_M, X = v of the
// OTHER branch, output to d_out.
__global__ __launch_bounds__(256) void k4_out(float* __restrict__ out) {
    __shared__ float sW[64 * 64];
    __shared__ unsigned long long sX[KC * PXU];

    int pxt = blockIdx.x;
    int bh = blockIdx.y;
    int b = bh >> 1, half = bh & 1;
    int mi = b * 2 + half;
    int vi = b * 2 + (1 - half);
    int tid = threadIdx.x, lane = tid & 31, wp = tid >> 5;

    for (int i = tid; i < 4096; i += 256) sW[i] = g_M[mi * 4096 + i];

    const float* vbp = g_v + (size_t)vi * D * Npix + pxt * PXT;
    float* outb = out + ((size_t)(b * 128 + half * 64)) * Npix + pxt * PXT;

    unsigned long long acc[8][8];
#pragma unroll
    for (int r = 0; r < 8; r++)
#pragma unroll
        for (int j = 0; j < 8; j++) acc[r][j] = 0ull;

    for (int kc = 0; kc < 64; kc += KC) {
        __syncthreads();
#pragma unroll
        for (int r = 0; r < KC; r++)
            sX[r * PXU + tid] =
                *(const unsigned long long*)(vbp + (size_t)(kc + r) * Npix + tid * 2);
        __syncthreads();
#pragma unroll
        for (int k = 0; k < KC; k++) {
            unsigned long long xv[8];
#pragma unroll
            for (int j = 0; j < 8; j++) xv[j] = sX[k * PXU + lane + 32 * j];
#pragma unroll
            for (int r = 0; r < 8; r++) {
                float wv = sW[(wp * 8 + r) * 64 + kc + k];
                unsigned long long w2 = pack2(wv, wv);
#pragma unroll
                for (int j = 0; j < 8; j++) acc[r][j] = ffma2(w2, xv[j], acc[r][j]);
            }
        }
    }
#pragma unroll
    for (int r = 0; r < 8; r++) {
        float* orow = outb + (size_t)(wp * 8 + r) * Npix;
#pragma unroll
        for (int j = 0; j < 8; j++)
            *(unsigned long long*)(orow + (lane + 32 * j) * 2) = acc[r][j];
    }
}

extern "C" void kernel_launch(void* const* d_in, const int* in_sizes, int n_in,
                              void* d_out, int out_size) {
    const float* x   = (const float*)d_in[0];
    const float* wq1 = (const float*)d_in[1];
    const float* wq2 = (const float*)d_in[2];
    const float* wd1 = (const float*)d_in[3];
    const float* wd2 = (const float*)d_in[4];
    const float* wp1 = (const float*)d_in[5];
    const float* wp2 = (const float*)d_in[6];
    const float* t1  = (const float*)d_in[7];
    const float* t2  = (const float*)d_in[8];
    float* out = (float*)d_out;

    k0_zero<<<16, 256>>>();
    k1_pw<<<dim3(384, 8), 256>>>(x, wq1, wq2);
    k2_dw<<<dim3(8, 32, 8), 256>>>(wd1, wd2);
    k3_attn<<<8, 256>>>(wp1, wp2, t1, t2);
    k4_out<<<dim3(128, 8), 256>>>(out);
}

// round 3
// speedup vs baseline: 1.2789x; 1.2149x over previous
#include <cuda_runtime.h>
#include <math.h>

#define BATCH 4
#define D 64
#define Himg 256
#define Wimg 256
#define Npix 65536
#define OC 192
#define HEADS 8

// Scratch (device globals — allocation-free per harness rules)
__device__ float g_pw[(size_t)8 * OC * Npix];   // pw conv output, [b*2+br][192][N]
__device__ float g_v[(size_t)8 * D * Npix];     // v after dw,   [b*2+br][64][N]
__device__ float g_sq[8 * 128];                 // sumsq q(64)+k(64) per (b,br)
__device__ float g_gram[8 * 64 * 8];            // Gram [c][j] per (b,br)
__device__ float g_M[8 * 64 * 64];              // folded (w_po @ attn) per (b,br)

__device__ __forceinline__ unsigned long long pack2(float x, float y) {
    unsigned long long u;
    asm("mov.b64 %0, {%1, %2};" : "=l"(u) : "f"(x), "f"(y));
    return u;
}
__device__ __forceinline__ unsigned long long ffma2(unsigned long long a,
                                                    unsigned long long b,
                                                    unsigned long long c) {
    unsigned long long d;
    asm("fma.rn.f32x2 %0, %1, %2, %3;" : "=l"(d) : "l"(a), "l"(b), "l"(c));
    return d;
}

// ---------------- K0: zero the reduction accumulators ----------------
__global__ void k0_zero() {
    int i = blockIdx.x * blockDim.x + threadIdx.x;
    if (i < 8 * 128) g_sq[i] = 0.f;
    if (i < 8 * 64 * 8) g_gram[i] = 0.f;
}

// ---------------- K1: pointwise conv as register-tiled GEMM ----------------
#define PXT 512
#define PXU 256
#define KC 16

__global__ __launch_bounds__(256) void k1_pw(const float* __restrict__ x,
                                             const float* __restrict__ wq1,
                                             const float* __restrict__ wq2) {
    __shared__ float sW[64 * 64];
    __shared__ unsigned long long sX[KC * PXU];

    int bx = blockIdx.x;
    int oct = bx % 3, pxt = bx / 3;
    int bb = blockIdx.y, b = bb >> 1, br = bb & 1;
    const float* wq = br ? wq2 : wq1;
    int tid = threadIdx.x, lane = tid & 31, wp = tid >> 5;

    for (int i = tid; i < 4096; i += 256) sW[i] = wq[oct * 4096 + i];

    const float* xb = x + ((size_t)(b * 128 + br * 64)) * Npix + pxt * PXT;
    float* outb = g_pw + (size_t)bb * OC * Npix + (size_t)(oct * 64) * Npix + pxt * PXT;

    unsigned long long acc[8][8];
#pragma unroll
    for (int r = 0; r < 8; r++)
#pragma unroll
        for (int j = 0; j < 8; j++) acc[r][j] = 0ull;

    for (int kc = 0; kc < 64; kc += KC) {
        __syncthreads();
#pragma unroll
        for (int r = 0; r < KC; r++)
            sX[r * PXU + tid] =
                *(const unsigned long long*)(xb + (size_t)(kc + r) * Npix + tid * 2);
        __syncthreads();
#pragma unroll
        for (int k = 0; k < KC; k++) {
            unsigned long long xv[8];
#pragma unroll
            for (int j = 0; j < 8; j++) xv[j] = sX[k * PXU + lane + 32 * j];
#pragma unroll
            for (int r = 0; r < 8; r++) {
                float wv = sW[(wp * 8 + r) * 64 + kc + k];
                unsigned long long w2 = pack2(wv, wv);
#pragma unroll
                for (int j = 0; j < 8; j++) acc[r][j] = ffma2(w2, xv[j], acc[r][j]);
            }
        }
    }
#pragma unroll
    for (int r = 0; r < 8; r++) {
        float* orow = outb + (size_t)(wp * 8 + r) * Npix;
#pragma unroll
        for (int j = 0; j < 8; j++)
            *(unsigned long long*)(orow + (lane + 32 * j) * 2) = acc[r][j];
    }
}

// ---------------- K2: depthwise 3x3 + Gram/sumsq + v, full-width bands ----------------
// Block: 256 threads = 256 columns, band of 8 output rows. Grid (32 bands, 8 bb).
// 4 channels staged per sync round; dw per thread-column; Gram via register
// accumulation + warp shuffle reduce + global RED.ADD.
__global__ __launch_bounds__(256, 2) void k2_dw(const float* __restrict__ wd1,
                                                const float* __restrict__ wd2) {
    __shared__ float ts[4][10][258];
    __shared__ float swd[OC * 9];

    int bb = blockIdx.y;
    int br = bb & 1;
    int band = blockIdx.x;
    int h0 = band * 8;
    int tid = threadIdx.x;
    int lane = tid & 31;
    const float* wdg = br ? wd2 : wd1;
    for (int i = tid; i < OC * 9; i += 256) swd[i] = wdg[i];
    // zero the horizontal padding columns once (never overwritten)
    if (tid < 40) {
        int c = tid / 10, r = tid - c * 10;
        ts[c][r][0] = 0.f;
        ts[c][r][257] = 0.f;
    }

    const float* pwb = g_pw + (size_t)bb * OC * Npix;
    float* vbp = g_v + (size_t)bb * D * Npix;
    float* gramb = g_gram + bb * 512;
    float* sqb = g_sq + bb * 128;

    // stage 4 consecutive channels' 10 rows (with vertical zero clamp)
    auto stage4 = [&](int gc0) {
        __syncthreads();
#pragma unroll
        for (int c = 0; c < 4; c++) {
            const float* chp = pwb + (size_t)(gc0 + c) * Npix;
#pragma unroll
            for (int r = 0; r < 10; r++) {
                int gh = h0 + r - 1;
                float v = 0.f;
                if ((unsigned)gh < Himg) v = chp[gh * Wimg + tid];
                ts[c][r][1 + tid] = v;
            }
        }
        __syncthreads();
    };

    // depthwise 3x3 for staged slot c at this thread's column -> out[8]
    auto dwcol = [&](int c, int gc, float out[8]) {
        float w[9];
#pragma unroll
        for (int i = 0; i < 9; i++) w[i] = swd[gc * 9 + i];
#pragma unroll
        for (int r = 0; r < 8; r++) {
            float a = 0.f;
#pragma unroll
            for (int kh = 0; kh < 3; kh++)
#pragma unroll
                for (int kw = 0; kw < 3; kw++)
                    a = fmaf(w[kh * 3 + kw], ts[c][r + kh][tid + kw], a);
            out[r] = a;
        }
    };

    auto wred_atomic = [&](float v, float* addr) {
        v += __shfl_xor_sync(0xffffffffu, v, 16);
        v += __shfl_xor_sync(0xffffffffu, v, 8);
        v += __shfl_xor_sync(0xffffffffu, v, 4);
        v += __shfl_xor_sync(0xffffffffu, v, 2);
        v += __shfl_xor_sync(0xffffffffu, v, 1);
        if (lane == 0) atomicAdd(addr, v);
    };

    float dq[8][8];

#pragma unroll 1
    for (int hd = 0; hd < HEADS; hd++) {
        // Q channels of this head
#pragma unroll 1
        for (int half = 0; half < 2; half++) {
            int gc0 = hd * 8 + half * 4;
            stage4(gc0);
#pragma unroll
            for (int c = 0; c < 4; c++) {
                float o[8];
                dwcol(c, gc0 + c, o);
                int i = half * 4 + c;
#pragma unroll
                for (int r = 0; r < 8; r++) dq[i][r] = o[r];
            }
        }
        // q sumsq
#pragma unroll
        for (int i = 0; i < 8; i++) {
            float s = 0.f;
#pragma unroll
            for (int r = 0; r < 8; r++) s = fmaf(dq[i][r], dq[i][r], s);
            wred_atomic(s, sqb + hd * 8 + i);
        }
        // K channels: per channel compute dk, ksq, and Gram row
#pragma unroll 1
        for (int half = 0; half < 2; half++) {
            int gc0 = 64 + hd * 8 + half * 4;
            stage4(gc0);
#pragma unroll
            for (int c = 0; c < 4; c++) {
                int j = half * 4 + c;
                float dk[8];
                dwcol(c, gc0 + c, dk);
                float s = 0.f;
#pragma unroll
                for (int r = 0; r < 8; r++) s = fmaf(dk[r], dk[r], s);
                wred_atomic(s, sqb + 64 + hd * 8 + j);
#pragma unroll
                for (int i = 0; i < 8; i++) {
                    float g = 0.f;
#pragma unroll
                    for (int r = 0; r < 8; r++) g = fmaf(dq[i][r], dk[r], g);
                    wred_atomic(g, gramb + (hd * 8 + i) * 8 + j);
                }
            }
        }
    }

    // V channels: dw and store
#pragma unroll 1
    for (int gq = 0; gq < 16; gq++) {
        int gc0 = 128 + gq * 4;
        stage4(gc0);
#pragma unroll
        for (int c = 0; c < 4; c++) {
            float o[8];
            dwcol(c, gc0 + c, o);
            float* op = vbp + (size_t)(gq * 4 + c) * Npix;
#pragma unroll
            for (int r = 0; r < 8; r++) op[(h0 + r) * Wimg + tid] = o[r];
        }
    }
}

// ---------------- K3: attn softmax + fold with w_po into M ----------------
__global__ __launch_bounds__(256) void k3_attn(const float* __restrict__ wpo1,
                                               const float* __restrict__ wpo2,
                                               const float* __restrict__ t1,
                                               const float* __restrict__ t2) {
    int bb = blockIdx.x;
    int br = bb & 1;
    __shared__ float attn[64][9];
    __shared__ float qn[64], kn[64];
    __shared__ float swpo[4096];
    int t = threadIdx.x;
    const float* wpo = br ? wpo2 : wpo1;
    for (int i = t; i < 4096; i += 256) swpo[i] = wpo[i];
    if (t < 64) {
        qn[t] = fmaxf(sqrtf(g_sq[bb * 128 + t]), 1e-12f);
        kn[t] = fmaxf(sqrtf(g_sq[bb * 128 + 64 + t]), 1e-12f);
    }
    __syncthreads();
    const float* tv = br ? t2 : t1;
    if (t < 64) {
        int hh = t >> 3;
        float tt = tv[hh];
        float s[8], m = -1e30f;
#pragma unroll
        for (int j = 0; j < 8; j++) {
            s[j] = g_gram[bb * 512 + t * 8 + j] / (qn[t] * kn[hh * 8 + j]) * tt;
            m = fmaxf(m, s[j]);
        }
        float sum = 0.f;
#pragma unroll
        for (int j = 0; j < 8; j++) { s[j] = expf(s[j] - m); sum += s[j]; }
        float inv = 1.f / sum;
#pragma unroll
        for (int j = 0; j < 8; j++) attn[t][j] = s[j] * inv;
    }
    __syncthreads();
    {
        int o = t >> 2, dg = t & 3;
#pragma unroll
        for (int dd = 0; dd < 16; dd++) {
            int d = dg * 16 + dd;
            int hd = d >> 3;
            float acc = 0.f;
#pragma unroll
            for (int ci = 0; ci < 8; ci++)
                acc = fmaf(swpo[o * 64 + hd * 8 + ci], attn[hd * 8 + ci][d & 7], acc);
            g_M[bb * 4096 + o * 64 + d] = acc;
        }
    }
}

// ---------------- K4: out = M @ v_other, register-tiled GEMM ----------------
__global__ __launch_bounds__(256) void k4_out(float* __restrict__ out) {
    __shared__ float sW[64 * 64];
    __shared__ unsigned long long sX[KC * PXU];

    int pxt = blockIdx.x;
    int bh = blockIdx.y;
    int b = bh >> 1, half = bh & 1;
    int mi = b * 2 + half;
    int vi = b * 2 + (1 - half);
    int tid = threadIdx.x, lane = tid & 31, wp = tid >> 5;

    for (int i = tid; i < 4096; i += 256) sW[i] = g_M[mi * 4096 + i];

    const float* vbp = g_v + (size_t)vi * D * Npix + pxt * PXT;
    float* outb = out + ((size_t)(b * 128 + half * 64)) * Npix + pxt * PXT;

    unsigned long long acc[8][8];
#pragma unroll
    for (int r = 0; r < 8; r++)
#pragma unroll
        for (int j = 0; j < 8; j++) acc[r][j] = 0ull;

    for (int kc = 0; kc < 64; kc += KC) {
        __syncthreads();
#pragma unroll
        for (int r = 0; r < KC; r++)
            sX[r * PXU + tid] =
                *(const unsigned long long*)(vbp + (size_t)(kc + r) * Npix + tid * 2);
        __syncthreads();
#pragma unroll
        for (int k = 0; k < KC; k++) {
            unsigned long long xv[8];
#pragma unroll
            for (int j = 0; j < 8; j++) xv[j] = sX[k * PXU + lane + 32 * j];
#pragma unroll
            for (int r = 0; r < 8; r++) {
                float wv = sW[(wp * 8 + r) * 64 + kc + k];
                unsigned long long w2 = pack2(wv, wv);
#pragma unroll
                for (int j = 0; j < 8; j++) acc[r][j] = ffma2(w2, xv[j], acc[r][j]);
            }
        }
    }
#pragma unroll
    for (int r = 0; r < 8; r++) {
        float* orow = outb + (size_t)(wp * 8 + r) * Npix;
#pragma unroll
        for (int j = 0; j < 8; j++)
            *(unsigned long long*)(orow + (lane + 32 * j) * 2) = acc[r][j];
    }
}

extern "C" void kernel_launch(void* const* d_in, const int* in_sizes, int n_in,
                              void* d_out, int out_size) {
    const float* x   = (const float*)d_in[0];
    const float* wq1 = (const float*)d_in[1];
    const float* wq2 = (const float*)d_in[2];
    const float* wd1 = (const float*)d_in[3];
    const float* wd2 = (const float*)d_in[4];
    const float* wp1 = (const float*)d_in[5];
    const float* wp2 = (const float*)d_in[6];
    const float* t1  = (const float*)d_in[7];
    const float* t2  = (const float*)d_in[8];
    float* out = (float*)d_out;

    k0_zero<<<16, 256>>>();
    k1_pw<<<dim3(384, 8), 256>>>(x, wq1, wq2);
    k2_dw<<<dim3(32, 8), 256>>>(wd1, wd2);
    k3_attn<<<8, 256>>>(wp1, wp2, t1, t2);
    k4_out<<<dim3(128, 8), 256>>>(out);
}

// round 4
// speedup vs baseline: 1.3157x; 1.0288x over previous
#include <cuda_runtime.h>
#include <math.h>

#define BATCH 4
#define D 64
#define Himg 256
#define Wimg 256
#define Npix 65536
#define OC 192
#define HEADS 8

// Scratch (device globals — allocation-free per harness rules)
__device__ float g_pw[(size_t)8 * OC * Npix];   // pw conv output, [b*2+br][192][N]
__device__ float g_v[(size_t)8 * D * Npix];     // v after dw,   [b*2+br][64][N]
__device__ float g_sq[8 * 128];                 // sumsq q(64)+k(64) per (b,br)
__device__ float g_gram[8 * 64 * 8];            // Gram [c][j] per (b,br)
__device__ float g_M[8 * 64 * 64];              // folded (w_po @ attn) per (b,br)

__device__ __forceinline__ unsigned long long pack2(float x, float y) {
    unsigned long long u;
    asm("mov.b64 %0, {%1, %2};" : "=l"(u) : "f"(x), "f"(y));
    return u;
}
__device__ __forceinline__ unsigned long long ffma2(unsigned long long a,
                                                    unsigned long long b,
                                                    unsigned long long c) {
    unsigned long long d;
    asm("fma.rn.f32x2 %0, %1, %2, %3;" : "=l"(d) : "l"(a), "l"(b), "l"(c));
    return d;
}
__device__ __forceinline__ void cpa8(unsigned int dst, const void* src) {
    asm volatile("cp.async.ca.shared.global [%0], [%1], 8;" :: "r"(dst), "l"(src));
}
__device__ __forceinline__ void cpa_commit() {
    asm volatile("cp.async.commit_group;");
}
__device__ __forceinline__ unsigned int smem_u32(const void* p) {
    return (unsigned int)__cvta_generic_to_shared(p);
}

// ---------------- K0: zero the reduction accumulators ----------------
__global__ void k0_zero() {
    int i = blockIdx.x * blockDim.x + threadIdx.x;
    if (i < 8 * 128) g_sq[i] = 0.f;
    if (i < 8 * 64 * 8) g_gram[i] = 0.f;
}

// ---------------- K1: pointwise conv GEMM, double-buffered cp.async ----------------
#define PXT 512
#define PXU 256
#define KC 8

__global__ __launch_bounds__(256) void k1_pw(const float* __restrict__ x,
                                             const float* __restrict__ wq1,
                                             const float* __restrict__ wq2) {
    __shared__ float sW[64 * 64];                       // 16KB
    __shared__ unsigned long long sX[2][KC * PXU];      // 32KB

    int bx = blockIdx.x;
    int oct = bx % 3, pxt = bx / 3;
    int bb = blockIdx.y, b = bb >> 1, br = bb & 1;
    const float* wq = br ? wq2 : wq1;
    int tid = threadIdx.x, lane = tid & 31, wp = tid >> 5;

    for (int i = tid; i < 4096; i += 256) sW[i] = wq[oct * 4096 + i];

    const float* xb = x + ((size_t)(b * 128 + br * 64)) * Npix + pxt * PXT;
    float* outb = g_pw + (size_t)bb * OC * Npix + (size_t)(oct * 64) * Npix + pxt * PXT;

    auto stage = [&](int kc0, int buf) {
        unsigned int dst = smem_u32(&sX[buf][tid]);
        const float* src = xb + (size_t)kc0 * Npix + tid * 2;
#pragma unroll
        for (int r = 0; r < KC; r++)
            cpa8(dst + r * PXU * 8, src + (size_t)r * Npix);
        cpa_commit();
    };

    unsigned long long acc[8][8];
#pragma unroll
    for (int r = 0; r < 8; r++)
#pragma unroll
        for (int j = 0; j < 8; j++) acc[r][j] = 0ull;

    stage(0, 0);
    int cur = 0;
#pragma unroll 1
    for (int rr = 0; rr < 8; rr++) {
        if (rr < 7) {
            stage((rr + 1) * KC, cur ^ 1);
            asm volatile("cp.async.wait_group 1;");
        } else {
            asm volatile("cp.async.wait_group 0;");
        }
        __syncthreads();
#pragma unroll
        for (int k = 0; k < KC; k++) {
            unsigned long long xv[8];
#pragma unroll
            for (int j = 0; j < 8; j++) xv[j] = sX[cur][k * PXU + lane + 32 * j];
#pragma unroll
            for (int r = 0; r < 8; r++) {
                float wv = sW[(wp * 8 + r) * 64 + rr * KC + k];
                unsigned long long w2 = pack2(wv, wv);
#pragma unroll
                for (int j = 0; j < 8; j++) acc[r][j] = ffma2(w2, xv[j], acc[r][j]);
            }
        }
        cur ^= 1;
        __syncthreads();
    }
#pragma unroll
    for (int r = 0; r < 8; r++) {
        float* orow = outb + (size_t)(wp * 8 + r) * Npix;
#pragma unroll
        for (int j = 0; j < 8; j++)
            *(unsigned long long*)(orow + (lane + 32 * j) * 2) = acc[r][j];
    }
}

// ---------------- K2a: depthwise 3x3 on q,k + Gram/sumsq reductions ----------------
// Block: 256 threads = 256 columns, band of 8 output rows. Grid (32 bands, 8 bb).
__global__ __launch_bounds__(256) void k2a_qk(const float* __restrict__ wd1,
                                              const float* __restrict__ wd2) {
    __shared__ float ts[4][10][258];
    __shared__ float swd[128 * 9];

    int bb = blockIdx.y;
    int br = bb & 1;
    int h0 = blockIdx.x * 8;
    int tid = threadIdx.x;
    int lane = tid & 31;
    const float* wdg = br ? wd2 : wd1;
    for (int i = tid; i < 128 * 9; i += 256) swd[i] = wdg[i];
    if (tid < 40) {
        int c = tid / 10, r = tid - c * 10;
        ts[c][r][0] = 0.f;
        ts[c][r][257] = 0.f;
    }

    const float* pwb = g_pw + (size_t)bb * OC * Npix;
    float* gramb = g_gram + bb * 512;
    float* sqb = g_sq + bb * 128;

    auto stage4 = [&](int gc0) {
        __syncthreads();
#pragma unroll
        for (int c = 0; c < 4; c++) {
            const float* chp = pwb + (size_t)(gc0 + c) * Npix;
#pragma unroll
            for (int r = 0; r < 10; r++) {
                int gh = h0 + r - 1;
                float v = 0.f;
                if ((unsigned)gh < Himg) v = chp[gh * Wimg + tid];
                ts[c][r][1 + tid] = v;
            }
        }
        __syncthreads();
    };

    auto dwcol = [&](int c, int gc, float out[8]) {
        float w[9];
#pragma unroll
        for (int i = 0; i < 9; i++) w[i] = swd[gc * 9 + i];
#pragma unroll
        for (int r = 0; r < 8; r++) {
            float a = 0.f;
#pragma unroll
            for (int kh = 0; kh < 3; kh++)
#pragma unroll
                for (int kw = 0; kw < 3; kw++)
                    a = fmaf(w[kh * 3 + kw], ts[c][r + kh][tid + kw], a);
            out[r] = a;
        }
    };

    auto wred_atomic = [&](float v, float* addr) {
        v += __shfl_xor_sync(0xffffffffu, v, 16);
        v += __shfl_xor_sync(0xffffffffu, v, 8);
        v += __shfl_xor_sync(0xffffffffu, v, 4);
        v += __shfl_xor_sync(0xffffffffu, v, 2);
        v += __shfl_xor_sync(0xffffffffu, v, 1);
        if (lane == 0) atomicAdd(addr, v);
    };

    float dq[8][8];

#pragma unroll 1
    for (int hd = 0; hd < HEADS; hd++) {
#pragma unroll 1
        for (int half = 0; half < 2; half++) {
            int gc0 = hd * 8 + half * 4;
            stage4(gc0);
#pragma unroll
            for (int c = 0; c < 4; c++) {
                float o[8];
                dwcol(c, gc0 + c, o);
                int i = half * 4 + c;
#pragma unroll
                for (int r = 0; r < 8; r++) dq[i][r] = o[r];
            }
        }
#pragma unroll
        for (int i = 0; i < 8; i++) {
            float s = 0.f;
#pragma unroll
            for (int r = 0; r < 8; r++) s = fmaf(dq[i][r], dq[i][r], s);
            wred_atomic(s, sqb + hd * 8 + i);
        }
#pragma unroll 1
        for (int half = 0; half < 2; half++) {
            int gc0 = 64 + hd * 8 + half * 4;
            stage4(gc0);
#pragma unroll
            for (int c = 0; c < 4; c++) {
                int j = half * 4 + c;
                float dk[8];
                dwcol(c, gc0 + c, dk);
                float s = 0.f;
#pragma unroll
                for (int r = 0; r < 8; r++) s = fmaf(dk[r], dk[r], s);
                wred_atomic(s, sqb + 64 + hd * 8 + j);
#pragma unroll
                for (int i = 0; i < 8; i++) {
                    float g = 0.f;
#pragma unroll
                    for (int r = 0; r < 8; r++) g = fmaf(dq[i][r], dk[r], g);
                    wred_atomic(g, gramb + (hd * 8 + i) * 8 + j);
                }
            }
        }
    }
}

// ---------------- K2b: depthwise 3x3 on v + store ----------------
__global__ __launch_bounds__(256, 2) void k2b_v(const float* __restrict__ wd1,
                                                const float* __restrict__ wd2) {
    __shared__ float ts[4][10][258];
    __shared__ float swd[64 * 9];

    int bb = blockIdx.y;
    int br = bb & 1;
    int h0 = blockIdx.x * 8;
    int tid = threadIdx.x;
    const float* wdg = (br ? wd2 : wd1) + 128 * 9;
    for (int i = tid; i < 64 * 9; i += 256) swd[i] = wdg[i];
    if (tid < 40) {
        int c = tid / 10, r = tid - c * 10;
        ts[c][r][0] = 0.f;
        ts[c][r][257] = 0.f;
    }

    const float* pwb = g_pw + (size_t)bb * OC * Npix + (size_t)128 * Npix;
    float* vbp = g_v + (size_t)bb * D * Npix;

#pragma unroll 1
    for (int gq = 0; gq < 16; gq++) {
        int gc0 = gq * 4;
        __syncthreads();
#pragma unroll
        for (int c = 0; c < 4; c++) {
            const float* chp = pwb + (size_t)(gc0 + c) * Npix;
#pragma unroll
            for (int r = 0; r < 10; r++) {
                int gh = h0 + r - 1;
                float v = 0.f;
                if ((unsigned)gh < Himg) v = chp[gh * Wimg + tid];
                ts[c][r][1 + tid] = v;
            }
        }
        __syncthreads();
#pragma unroll
        for (int c = 0; c < 4; c++) {
            float w[9];
#pragma unroll
            for (int i = 0; i < 9; i++) w[i] = swd[(gc0 + c) * 9 + i];
            float* op = vbp + (size_t)(gc0 + c) * Npix;
#pragma unroll
            for (int r = 0; r < 8; r++) {
                float a = 0.f;
#pragma unroll
                for (int kh = 0; kh < 3; kh++)
#pragma unroll
                    for (int kw = 0; kw < 3; kw++)
                        a = fmaf(w[kh * 3 + kw], ts[c][r + kh][tid + kw], a);
                op[(h0 + r) * Wimg + tid] = a;
            }
        }
    }
}

// ---------------- K3: attn softmax + fold with w_po into M ----------------
__global__ __launch_bounds__(256) void k3_attn(const float* __restrict__ wpo1,
                                               const float* __restrict__ wpo2,
                                               const float* __restrict__ t1,
                                               const float* __restrict__ t2) {
    int bb = blockIdx.x;
    int br = bb & 1;
    __shared__ float attn[64][9];
    __shared__ float qn[64], kn[64];
    __shared__ float swpo[4096];
    int t = threadIdx.x;
    const float* wpo = br ? wpo2 : wpo1;
    for (int i = t; i < 4096; i += 256) swpo[i] = wpo[i];
    if (t < 64) {
        qn[t] = fmaxf(sqrtf(g_sq[bb * 128 + t]), 1e-12f);
        kn[t] = fmaxf(sqrtf(g_sq[bb * 128 + 64 + t]), 1e-12f);
    }
    __syncthreads();
    const float* tv = br ? t2 : t1;
    if (t < 64) {
        int hh = t >> 3;
        float tt = tv[hh];
        float s[8], m = -1e30f;
#pragma unroll
        for (int j = 0; j < 8; j++) {
            s[j] = g_gram[bb * 512 + t * 8 + j] / (qn[t] * kn[hh * 8 + j]) * tt;
            m = fmaxf(m, s[j]);
        }
        float sum = 0.f;
#pragma unroll
        for (int j = 0; j < 8; j++) { s[j] = expf(s[j] - m); sum += s[j]; }
        float inv = 1.f / sum;
#pragma unroll
        for (int j = 0; j < 8; j++) attn[t][j] = s[j] * inv;
    }
    __syncthreads();
    {
        int o = t >> 2, dg = t & 3;
#pragma unroll
        for (int dd = 0; dd < 16; dd++) {
            int d = dg * 16 + dd;
            int hd = d >> 3;
            float acc = 0.f;
#pragma unroll
            for (int ci = 0; ci < 8; ci++)
                acc = fmaf(swpo[o * 64 + hd * 8 + ci], attn[hd * 8 + ci][d & 7], acc);
            g_M[bb * 4096 + o * 64 + d] = acc;
        }
    }
}

// ---------------- K4: out = M @ v_other, double-buffered cp.async ----------------
__global__ __launch_bounds__(256) void k4_out(float* __restrict__ out) {
    __shared__ float sW[64 * 64];
    __shared__ unsigned long long sX[2][KC * PXU];

    int pxt = blockIdx.x;
    int bh = blockIdx.y;
    int b = bh >> 1, half = bh & 1;
    int mi = b * 2 + half;
    int vi = b * 2 + (1 - half);
    int tid = threadIdx.x, lane = tid & 31, wp = tid >> 5;

    for (int i = tid; i < 4096; i += 256) sW[i] = g_M[mi * 4096 + i];

    const float* vbp = g_v + (size_t)vi * D * Npix + pxt * PXT;
    float* outb = out + ((size_t)(b * 128 + half * 64)) * Npix + pxt * PXT;

    auto stage = [&](int kc0, int buf) {
        unsigned int dst = smem_u32(&sX[buf][tid]);
        const float* src = vbp + (size_t)kc0 * Npix + tid * 2;
#pragma unroll
        for (int r = 0; r < KC; r++)
            cpa8(dst + r * PXU * 8, src + (size_t)r * Npix);
        cpa_commit();
    };

    unsigned long long acc[8][8];
#pragma unroll
    for (int r = 0; r < 8; r++)
#pragma unroll
        for (int j = 0; j < 8; j++) acc[r][j] = 0ull;

    stage(0, 0);
    int cur = 0;
#pragma unroll 1
    for (int rr = 0; rr < 8; rr++) {
        if (rr < 7) {
            stage((rr + 1) * KC, cur ^ 1);
            asm volatile("cp.async.wait_group 1;");
        } else {
            asm volatile("cp.async.wait_group 0;");
        }
        __syncthreads();
#pragma unroll
        for (int k = 0; k < KC; k++) {
            unsigned long long xv[8];
#pragma unroll
            for (int j = 0; j < 8; j++) xv[j] = sX[cur][k * PXU + lane + 32 * j];
#pragma unroll
            for (int r = 0; r < 8; r++) {
                float wv = sW[(wp * 8 + r) * 64 + rr * KC + k];
                unsigned long long w2 = pack2(wv, wv);
#pragma unroll
                for (int j = 0; j < 8; j++) acc[r][j] = ffma2(w2, xv[j], acc[r][j]);
            }
        }
        cur ^= 1;
        __syncthreads();
    }
#pragma unroll
    for (int r = 0; r < 8; r++) {
        float* orow = outb + (size_t)(wp * 8 + r) * Npix;
#pragma unroll
        for (int j = 0; j < 8; j++)
            *(unsigned long long*)(orow + (lane + 32 * j) * 2) = acc[r][j];
    }
}

extern "C" void kernel_launch(void* const* d_in, const int* in_sizes, int n_in,
                              void* d_out, int out_size) {
    const float* x   = (const float*)d_in[0];
    const float* wq1 = (const float*)d_in[1];
    const float* wq2 = (const float*)d_in[2];
    const float* wd1 = (const float*)d_in[3];
    const float* wd2 = (const float*)d_in[4];
    const float* wp1 = (const float*)d_in[5];
    const float* wp2 = (const float*)d_in[6];
    const float* t1  = (const float*)d_in[7];
    const float* t2  = (const float*)d_in[8];
    float* out = (float*)d_out;

    k0_zero<<<16, 256>>>();
    k1_pw<<<dim3(384, 8), 256>>>(x, wq1, wq2);
    k2a_qk<<<dim3(32, 8), 256>>>(wd1, wd2);
    k2b_v<<<dim3(32, 8), 256>>>(wd1, wd2);
    k3_attn<<<8, 256>>>(wp1, wp2, t1, t2);
    k4_out<<<dim3(128, 8), 256>>>(out);
}

// round 5
// speedup vs baseline: 1.4354x; 1.0910x over previous
#include <cuda_runtime.h>
#include <math.h>

#define BATCH 4
#define D 64
#define Himg 256
#define Wimg 256
#define Npix 65536
#define OC 192
#define HEADS 8

__device__ float g_pw[(size_t)8 * OC * Npix];   // pw conv output, [b*2+br][192][N]
__device__ float g_v[(size_t)8 * D * Npix];     // v after dw,   [b*2+br][64][N]
__device__ float g_sq[8 * 128];                 // sumsq q(64)+k(64) per (b,br)
__device__ float g_gram[8 * 64 * 8];            // Gram [c][j] per (b,br)
__device__ float g_M[8 * 64 * 64];              // folded (w_po @ attn) per (b,br)

__device__ __forceinline__ unsigned long long pack2(float x, float y) {
    unsigned long long u;
    asm("mov.b64 %0, {%1, %2};" : "=l"(u) : "f"(x), "f"(y));
    return u;
}
__device__ __forceinline__ unsigned long long ffma2(unsigned long long a,
                                                    unsigned long long b,
                                                    unsigned long long c) {
    unsigned long long d;
    asm("fma.rn.f32x2 %0, %1, %2, %3;" : "=l"(d) : "l"(a), "l"(b), "l"(c));
    return d;
}
__device__ __forceinline__ void cpa8(unsigned int dst, const void* src) {
    asm volatile("cp.async.ca.shared.global [%0], [%1], 8;" :: "r"(dst), "l"(src));
}
__device__ __forceinline__ void cpa_commit() {
    asm volatile("cp.async.commit_group;");
}
__device__ __forceinline__ unsigned int smem_u32(const void* p) {
    return (unsigned int)__cvta_generic_to_shared(p);
}

// ---------------- pads: split zeroing so k1 lands in the ncu capture slot (idx 3) ----------------
__global__ void padA_zero_sq() {
    int i = blockIdx.x * blockDim.x + threadIdx.x;
    if (i < 8 * 128) g_sq[i] = 0.f;
}
__global__ void padB_zero_gram() {
    int i = blockIdx.x * blockDim.x + threadIdx.x;
    if (i < 8 * 64 * 8) g_gram[i] = 0.f;
}
__global__ void padC_noop() {}

// ---------------- K1: pointwise conv GEMM, occ-2, double-buffered cp.async ----------------
// Block tile: 64 oc x 256 px, thread tile: 8 oc x 8 px (32 u64 accs). 2 blocks/SM.
#define PXT 256
#define PXU 128   // u64 columns per tile
#define KC 8

__global__ __launch_bounds__(256, 2) void k1_pw(const float* __restrict__ x,
                                                const float* __restrict__ wq1,
                                                const float* __restrict__ wq2) {
    __shared__ float sW[64 * 64];                       // 16KB
    __shared__ unsigned long long sX[2][KC * PXU];      // 16KB

    int bx = blockIdx.x;
    int oct = bx % 3, pxt = bx / 3;
    int bb = blockIdx.y, b = bb >> 1, br = bb & 1;
    const float* wq = br ? wq2 : wq1;
    int tid = threadIdx.x, lane = tid & 31, wp = tid >> 5;

    for (int i = tid; i < 4096; i += 256) sW[i] = wq[oct * 4096 + i];

    const float* xb = x + ((size_t)(b * 128 + br * 64)) * Npix + pxt * PXT;
    float* outb = g_pw + (size_t)bb * OC * Npix + (size_t)(oct * 64) * Npix + pxt * PXT;

    auto stage = [&](int kc0, int buf) {
        unsigned int dst = smem_u32(&sX[buf][0]);
#pragma unroll
        for (int t = 0; t < 4; t++) {
            int i = tid + t * 256;
            int r = i >> 7, c = i & 127;
            cpa8(dst + i * 8, xb + (size_t)(kc0 + r) * Npix + c * 2);
        }
        cpa_commit();
    };

    unsigned long long acc[8][4];
#pragma unroll
    for (int r = 0; r < 8; r++)
#pragma unroll
        for (int j = 0; j < 4; j++) acc[r][j] = 0ull;

    stage(0, 0);
    int cur = 0;
#pragma unroll 1
    for (int rr = 0; rr < 8; rr++) {
        if (rr < 7) {
            stage((rr + 1) * KC, cur ^ 1);
            asm volatile("cp.async.wait_group 1;");
        } else {
            asm volatile("cp.async.wait_group 0;");
        }
        __syncthreads();
#pragma unroll
        for (int k = 0; k < KC; k++) {
            unsigned long long xv[4];
#pragma unroll
            for (int j = 0; j < 4; j++) xv[j] = sX[cur][k * PXU + lane + 32 * j];
#pragma unroll
            for (int r = 0; r < 8; r++) {
                float wv = sW[(wp * 8 + r) * 64 + rr * KC + k];
                unsigned long long w2 = pack2(wv, wv);
#pragma unroll
                for (int j = 0; j < 4; j++) acc[r][j] = ffma2(w2, xv[j], acc[r][j]);
            }
        }
        cur ^= 1;
        __syncthreads();
    }
#pragma unroll
    for (int r = 0; r < 8; r++) {
        float* orow = outb + (size_t)(wp * 8 + r) * Npix;
#pragma unroll
        for (int j = 0; j < 4; j++)
            *(unsigned long long*)(orow + (lane + 32 * j) * 2) = acc[r][j];
    }
}

// ---------------- K2a: depthwise 3x3 on q,k + Gram/sumsq reductions ----------------
__global__ __launch_bounds__(256) void k2a_qk(const float* __restrict__ wd1,
                                              const float* __restrict__ wd2) {
    __shared__ float ts[4][10][258];
    __shared__ float swd[128 * 9];

    int bb = blockIdx.y;
    int br = bb & 1;
    int h0 = blockIdx.x * 8;
    int tid = threadIdx.x;
    int lane = tid & 31;
    const float* wdg = br ? wd2 : wd1;
    for (int i = tid; i < 128 * 9; i += 256) swd[i] = wdg[i];
    if (tid < 40) {
        int c = tid / 10, r = tid - c * 10;
        ts[c][r][0] = 0.f;
        ts[c][r][257] = 0.f;
    }

    const float* pwb = g_pw + (size_t)bb * OC * Npix;
    float* gramb = g_gram + bb * 512;
    float* sqb = g_sq + bb * 128;

    auto stage4 = [&](int gc0) {
        __syncthreads();
#pragma unroll
        for (int c = 0; c < 4; c++) {
            const float* chp = pwb + (size_t)(gc0 + c) * Npix;
#pragma unroll
            for (int r = 0; r < 10; r++) {
                int gh = h0 + r - 1;
                float v = 0.f;
                if ((unsigned)gh < Himg) v = chp[gh * Wimg + tid];
                ts[c][r][1 + tid] = v;
            }
        }
        __syncthreads();
    };

    auto dwcol = [&](int c, int gc, float out[8]) {
        float w[9];
#pragma unroll
        for (int i = 0; i < 9; i++) w[i] = swd[gc * 9 + i];
#pragma unroll
        for (int r = 0; r < 8; r++) {
            float a = 0.f;
#pragma unroll
            for (int kh = 0; kh < 3; kh++)
#pragma unroll
                for (int kw = 0; kw < 3; kw++)
                    a = fmaf(w[kh * 3 + kw], ts[c][r + kh][tid + kw], a);
            out[r] = a;
        }
    };

    auto wred_atomic = [&](float v, float* addr) {
        v += __shfl_xor_sync(0xffffffffu, v, 16);
        v += __shfl_xor_sync(0xffffffffu, v, 8);
        v += __shfl_xor_sync(0xffffffffu, v, 4);
        v += __shfl_xor_sync(0xffffffffu, v, 2);
        v += __shfl_xor_sync(0xffffffffu, v, 1);
        if (lane == 0) atomicAdd(addr, v);
    };

    float dq[8][8];

#pragma unroll 1
    for (int hd = 0; hd < HEADS; hd++) {
#pragma unroll 1
        for (int half = 0; half < 2; half++) {
            int gc0 = hd * 8 + half * 4;
            stage4(gc0);
#pragma unroll
            for (int c = 0; c < 4; c++) {
                float o[8];
                dwcol(c, gc0 + c, o);
                int i = half * 4 + c;
#pragma unroll
                for (int r = 0; r < 8; r++) dq[i][r] = o[r];
            }
        }
#pragma unroll
        for (int i = 0; i < 8; i++) {
            float s = 0.f;
#pragma unroll
            for (int r = 0; r < 8; r++) s = fmaf(dq[i][r], dq[i][r], s);
            wred_atomic(s, sqb + hd * 8 + i);
        }
#pragma unroll 1
        for (int half = 0; half < 2; half++) {
            int gc0 = 64 + hd * 8 + half * 4;
            stage4(gc0);
#pragma unroll
            for (int c = 0; c < 4; c++) {
                int j = half * 4 + c;
                float dk[8];
                dwcol(c, gc0 + c, dk);
                float s = 0.f;
#pragma unroll
                for (int r = 0; r < 8; r++) s = fmaf(dk[r], dk[r], s);
                wred_atomic(s, sqb + 64 + hd * 8 + j);
#pragma unroll
                for (int i = 0; i < 8; i++) {
                    float g = 0.f;
#pragma unroll
                    for (int r = 0; r < 8; r++) g = fmaf(dq[i][r], dk[r], g);
                    wred_atomic(g, gramb + (hd * 8 + i) * 8 + j);
                }
            }
        }
    }
}

// ---------------- K2b: depthwise 3x3 on v + store ----------------
__global__ __launch_bounds__(256, 2) void k2b_v(const float* __restrict__ wd1,
                                                const float* __restrict__ wd2) {
    __shared__ float ts[4][10][258];
    __shared__ float swd[64 * 9];

    int bb = blockIdx.y;
    int br = bb & 1;
    int h0 = blockIdx.x * 8;
    int tid = threadIdx.x;
    const float* wdg = (br ? wd2 : wd1) + 128 * 9;
    for (int i = tid; i < 64 * 9; i += 256) swd[i] = wdg[i];
    if (tid < 40) {
        int c = tid / 10, r = tid - c * 10;
        ts[c][r][0] = 0.f;
        ts[c][r][257] = 0.f;
    }

    const float* pwb = g_pw + (size_t)bb * OC * Npix + (size_t)128 * Npix;
    float* vbp = g_v + (size_t)bb * D * Npix;

#pragma unroll 1
    for (int gq = 0; gq < 16; gq++) {
        int gc0 = gq * 4;
        __syncthreads();
#pragma unroll
        for (int c = 0; c < 4; c++) {
            const float* chp = pwb + (size_t)(gc0 + c) * Npix;
#pragma unroll
            for (int r = 0; r < 10; r++) {
                int gh = h0 + r - 1;
                float v = 0.f;
                if ((unsigned)gh < Himg) v = chp[gh * Wimg + tid];
                ts[c][r][1 + tid] = v;
            }
        }
        __syncthreads();
#pragma unroll
        for (int c = 0; c < 4; c++) {
            float w[9];
#pragma unroll
            for (int i = 0; i < 9; i++) w[i] = swd[(gc0 + c) * 9 + i];
            float* op = vbp + (size_t)(gc0 + c) * Npix;
#pragma unroll
            for (int r = 0; r < 8; r++) {
                float a = 0.f;
#pragma unroll
                for (int kh = 0; kh < 3; kh++)
#pragma unroll
                    for (int kw = 0; kw < 3; kw++)
                        a = fmaf(w[kh * 3 + kw], ts[c][r + kh][tid + kw], a);
                op[(h0 + r) * Wimg + tid] = a;
            }
        }
    }
}

// ---------------- K3: attn softmax + fold with w_po into M ----------------
__global__ __launch_bounds__(256) void k3_attn(const float* __restrict__ wpo1,
                                               const float* __restrict__ wpo2,
                                               const float* __restrict__ t1,
                                               const float* __restrict__ t2) {
    int bb = blockIdx.x;
    int br = bb & 1;
    __shared__ float attn[64][9];
    __shared__ float qn[64], kn[64];
    __shared__ float swpo[4096];
    int t = threadIdx.x;
    const float* wpo = br ? wpo2 : wpo1;
    for (int i = t; i < 4096; i += 256) swpo[i] = wpo[i];
    if (t < 64) {
        qn[t] = fmaxf(sqrtf(g_sq[bb * 128 + t]), 1e-12f);
        kn[t] = fmaxf(sqrtf(g_sq[bb * 128 + 64 + t]), 1e-12f);
    }
    __syncthreads();
    const float* tv = br ? t2 : t1;
    if (t < 64) {
        int hh = t >> 3;
        float tt = tv[hh];
        float s[8], m = -1e30f;
#pragma unroll
        for (int j = 0; j < 8; j++) {
            s[j] = g_gram[bb * 512 + t * 8 + j] / (qn[t] * kn[hh * 8 + j]) * tt;
            m = fmaxf(m, s[j]);
        }
        float sum = 0.f;
#pragma unroll
        for (int j = 0; j < 8; j++) { s[j] = expf(s[j] - m); sum += s[j]; }
        float inv = 1.f / sum;
#pragma unroll
        for (int j = 0; j < 8; j++) attn[t][j] = s[j] * inv;
    }
    __syncthreads();
    {
        int o = t >> 2, dg = t & 3;
#pragma unroll
        for (int dd = 0; dd < 16; dd++) {
            int d = dg * 16 + dd;
            int hd = d >> 3;
            float acc = 0.f;
#pragma unroll
            for (int ci = 0; ci < 8; ci++)
                acc = fmaf(swpo[o * 64 + hd * 8 + ci], attn[hd * 8 + ci][d & 7], acc);
            g_M[bb * 4096 + o * 64 + d] = acc;
        }
    }
}

// ---------------- K4: out = M @ v_other, occ-2, double-buffered cp.async ----------------
__global__ __launch_bounds__(256, 2) void k4_out(float* __restrict__ out) {
    __shared__ float sW[64 * 64];
    __shared__ unsigned long long sX[2][KC * PXU];

    int pxt = blockIdx.x;
    int bh = blockIdx.y;
    int b = bh >> 1, half = bh & 1;
    int mi = b * 2 + half;
    int vi = b * 2 + (1 - half);
    int tid = threadIdx.x, lane = tid & 31, wp = tid >> 5;

    for (int i = tid; i < 4096; i += 256) sW[i] = g_M[mi * 4096 + i];

    const float* vbp = g_v + (size_t)vi * D * Npix + pxt * PXT;
    float* outb = out + ((size_t)(b * 128 + half * 64)) * Npix + pxt * PXT;

    auto stage = [&](int kc0, int buf) {
        unsigned int dst = smem_u32(&sX[buf][0]);
#pragma unroll
        for (int t = 0; t < 4; t++) {
            int i = tid + t * 256;
            int r = i >> 7, c = i & 127;
            cpa8(dst + i * 8, vbp + (size_t)(kc0 + r) * Npix + c * 2);
        }
        cpa_commit();
    };

    unsigned long long acc[8][4];
#pragma unroll
    for (int r = 0; r < 8; r++)
#pragma unroll
        for (int j = 0; j < 4; j++) acc[r][j] = 0ull;

    stage(0, 0);
    int cur = 0;
#pragma unroll 1
    for (int rr = 0; rr < 8; rr++) {
        if (rr < 7) {
            stage((rr + 1) * KC, cur ^ 1);
            asm volatile("cp.async.wait_group 1;");
        } else {
            asm volatile("cp.async.wait_group 0;");
        }
        __syncthreads();
#pragma unroll
        for (int k = 0; k < KC; k++) {
            unsigned long long xv[4];
#pragma unroll
            for (int j = 0; j < 4; j++) xv[j] = sX[cur][k * PXU + lane + 32 * j];
#pragma unroll
            for (int r = 0; r < 8; r++) {
                float wv = sW[(wp * 8 + r) * 64 + rr * KC + k];
                unsigned long long w2 = pack2(wv, wv);
#pragma unroll
                for (int j = 0; j < 4; j++) acc[r][j] = ffma2(w2, xv[j], acc[r][j]);
            }
        }
        cur ^= 1;
        __syncthreads();
    }
#pragma unroll
    for (int r = 0; r < 8; r++) {
        float* orow = outb + (size_t)(wp * 8 + r) * Npix;
#pragma unroll
        for (int j = 0; j < 4; j++)
            *(unsigned long long*)(orow + (lane + 32 * j) * 2) = acc[r][j];
    }
}

extern "C" void kernel_launch(void* const* d_in, const int* in_sizes, int n_in,
                              void* d_out, int out_size) {
    const float* x   = (const float*)d_in[0];
    const float* wq1 = (const float*)d_in[1];
    const float* wq2 = (const float*)d_in[2];
    const float* wd1 = (const float*)d_in[3];
    const float* wd2 = (const float*)d_in[4];
    const float* wp1 = (const float*)d_in[5];
    const float* wp2 = (const float*)d_in[6];
    const float* t1  = (const float*)d_in[7];
    const float* t2  = (const float*)d_in[8];
    float* out = (float*)d_out;

    // k1 must be launch index 3 (ncu capture slot)
    padA_zero_sq<<<4, 256>>>();
    padB_zero_gram<<<16, 256>>>();
    padC_noop<<<1, 32>>>();
    k1_pw<<<dim3(768, 8), 256>>>(x, wq1, wq2);
    k2a_qk<<<dim3(32, 8), 256>>>(wd1, wd2);
    k2b_v<<<dim3(32, 8), 256>>>(wd1, wd2);
    k3_attn<<<8, 256>>>(wp1, wp2, t1, t2);
    k4_out<<<dim3(256, 8), 256>>>(out);
}

// round 7
// speedup vs baseline: 1.6091x; 1.1210x over previous
#include <cuda_runtime.h>
#include <math.h>
#include <stdint.h>
#include <mma.h>

using namespace nvcuda;

#define BATCH 4
#define D 64
#define Himg 256
#define Wimg 256
#define Npix 65536
#define OC 192
#define HEADS 8

__device__ float g_pw[(size_t)8 * OC * Npix];   // pw conv output, [b*2+br][192][N]
__device__ float g_v[(size_t)8 * D * Npix];     // v after dw,   [b*2+br][64][N]
__device__ float g_sq[8 * 128];                 // sumsq q(64)+k(64) per (b,br)
__device__ float g_gram[8 * 64 * 8];            // Gram [c][j] per (b,br)
__device__ float g_M[8 * 64 * 64];              // folded (w_po @ attn) per (b,br)

__device__ __forceinline__ unsigned long long pack2(float x, float y) {
    unsigned long long u;
    asm("mov.b64 %0, {%1, %2};" : "=l"(u) : "f"(x), "f"(y));
    return u;
}
__device__ __forceinline__ unsigned long long ffma2(unsigned long long a,
                                                    unsigned long long b,
                                                    unsigned long long c) {
    unsigned long long d;
    asm("fma.rn.f32x2 %0, %1, %2, %3;" : "=l"(d) : "l"(a), "l"(b), "l"(c));
    return d;
}
__device__ __forceinline__ void cpa8(unsigned int dst, const void* src) {
    asm volatile("cp.async.ca.shared.global [%0], [%1], 8;" :: "r"(dst), "l"(src));
}
__device__ __forceinline__ void cpa16(unsigned int dst, const void* src) {
    asm volatile("cp.async.ca.shared.global [%0], [%1], 16;" :: "r"(dst), "l"(src));
}
__device__ __forceinline__ void cpa_commit() {
    asm volatile("cp.async.commit_group;");
}
__device__ __forceinline__ unsigned int smem_u32(const void* p) {
    return (unsigned int)__cvta_generic_to_shared(p);
}

// ---------------- pads: keep k1 in the ncu capture slot (idx 3) ----------------
__global__ void padA_zero_sq() {
    int i = blockIdx.x * blockDim.x + threadIdx.x;
    if (i < 8 * 128) g_sq[i] = 0.f;
}
__global__ void padB_zero_gram() {
    int i = blockIdx.x * blockDim.x + threadIdx.x;
    if (i < 8 * 64 * 8) g_gram[i] = 0.f;
}
__global__ void padC_noop() {}

// ---------------- K1: pointwise conv via wmma tf32 (legacy HMMA path) ----------------
// Block: 256 thr = 8 warps; tile 64 oc x 256 px; K=64 in 8 chunks of 8,
// double-buffered cp.async. Warp = 32 oc x 64 px = 2x4 (16x16) acc frags.
#define K1_LDW 72    // sW row pitch (floats), mult of 8
#define K1_LDX 264   // sX row pitch (floats), mult of 8

__global__ __launch_bounds__(256) void k1_wmma(const float* __restrict__ x,
                                               const float* __restrict__ wq1,
                                               const float* __restrict__ wq2) {
    __shared__ float sW[64 * K1_LDW];           // 18KB
    __shared__ float sX[2][8 * K1_LDX];         // 2 x 8.25KB

    int bx = blockIdx.x;
    int oct = bx % 3, pxt = bx / 3;
    int bb = blockIdx.y, b = bb >> 1, br = bb & 1;
    const float* wq = br ? wq2 : wq1;
    int tid = threadIdx.x;
    int wid = tid >> 5;
    int ocw = wid >> 2;        // 0..1 -> 32-oc half
    int pxw = wid & 3;         // 0..3 -> 64-px quarter
    int px0 = pxt * 256;

    for (int i = tid; i < 4096; i += 256) {
        int row = i >> 6, c = i & 63;
        sW[row * K1_LDW + c] = wq[oct * 4096 + i];
    }

    const float* xb = x + ((size_t)(b * 128 + br * 64)) * Npix + px0;
    float* pwb = g_pw + (size_t)bb * OC * Npix + (size_t)(oct * 64) * Npix + px0;

    // stage 8 k-rows x 256 px (512 16B chunks, 2 per thread)
    auto stage = [&](int kc0, int buf) {
        unsigned int dstb = smem_u32(&sX[buf][0]);
#pragma unroll
        for (int t = 0; t < 2; t++) {
            int ch = tid + t * 256;
            int r = ch >> 6, c16 = ch & 63;
            cpa16(dstb + (r * K1_LDX + c16 * 4) * 4,
                  xb + (size_t)(kc0 + r) * Npix + c16 * 4);
        }
        cpa_commit();
    };

    wmma::fragment<wmma::accumulator, 16, 16, 8, float> acc[2][4];
#pragma unroll
    for (int co = 0; co < 2; co++)
#pragma unroll
        for (int pb = 0; pb < 4; pb++) wmma::fill_fragment(acc[co][pb], 0.f);

    stage(0, 0);
    int cur = 0;
    __syncthreads();
#pragma unroll 1
    for (int rr = 0; rr < 8; rr++) {
        if (rr < 7) {
            stage((rr + 1) * 8, cur ^ 1);
            asm volatile("cp.async.wait_group 1;");
        } else {
            asm volatile("cp.async.wait_group 0;");
        }
        __syncthreads();

        wmma::fragment<wmma::matrix_a, 16, 16, 8, wmma::precision::tf32, wmma::row_major> af[2];
#pragma unroll
        for (int co = 0; co < 2; co++) {
            wmma::load_matrix_sync(af[co], &sW[(ocw * 32 + co * 16) * K1_LDW + rr * 8], K1_LDW);
#pragma unroll
            for (int e = 0; e < af[co].num_elements; e++)
                af[co].x[e] = wmma::__float_to_tf32(af[co].x[e]);
        }
#pragma unroll
        for (int pb = 0; pb < 4; pb++) {
            wmma::fragment<wmma::matrix_b, 16, 16, 8, wmma::precision::tf32, wmma::row_major> bf;
            wmma::load_matrix_sync(bf, &sX[cur][pxw * 64 + pb * 16], K1_LDX);
#pragma unroll
            for (int e = 0; e < bf.num_elements; e++)
                bf.x[e] = wmma::__float_to_tf32(bf.x[e]);
#pragma unroll
            for (int co = 0; co < 2; co++)
                wmma::mma_sync(acc[co][pb], af[co], bf, acc[co][pb]);
        }
        cur ^= 1;
        __syncthreads();
    }

#pragma unroll
    for (int co = 0; co < 2; co++)
#pragma unroll
        for (int pb = 0; pb < 4; pb++)
            wmma::store_matrix_sync(
                pwb + (size_t)(ocw * 32 + co * 16) * Npix + pxw * 64 + pb * 16,
                acc[co][pb], Npix, wmma::mem_row_major);
}

// ---------------- K2a: depthwise 3x3 on q,k + Gram/sumsq reductions ----------------
__global__ __launch_bounds__(256) void k2a_qk(const float* __restrict__ wd1,
                                              const float* __restrict__ wd2) {
    __shared__ float ts[4][10][258];
    __shared__ float swd[128 * 9];

    int bb = blockIdx.y;
    int br = bb & 1;
    int h0 = blockIdx.x * 8;
    int tid = threadIdx.x;
    int lane = tid & 31;
    const float* wdg = br ? wd2 : wd1;
    for (int i = tid; i < 128 * 9; i += 256) swd[i] = wdg[i];
    if (tid < 40) {
        int c = tid / 10, r = tid - c * 10;
        ts[c][r][0] = 0.f;
        ts[c][r][257] = 0.f;
    }

    const float* pwb = g_pw + (size_t)bb * OC * Npix;
    float* gramb = g_gram + bb * 512;
    float* sqb = g_sq + bb * 128;

    auto stage4 = [&](int gc0) {
        __syncthreads();
#pragma unroll
        for (int c = 0; c < 4; c++) {
            const float* chp = pwb + (size_t)(gc0 + c) * Npix;
#pragma unroll
            for (int r = 0; r < 10; r++) {
                int gh = h0 + r - 1;
                float v = 0.f;
                if ((unsigned)gh < Himg) v = chp[gh * Wimg + tid];
                ts[c][r][1 + tid] = v;
            }
        }
        __syncthreads();
    };

    auto dwcol = [&](int c, int gc, float out[8]) {
        float w[9];
#pragma unroll
        for (int i = 0; i < 9; i++) w[i] = swd[gc * 9 + i];
#pragma unroll
        for (int r = 0; r < 8; r++) {
            float a = 0.f;
#pragma unroll
            for (int kh = 0; kh < 3; kh++)
#pragma unroll
                for (int kw = 0; kw < 3; kw++)
                    a = fmaf(w[kh * 3 + kw], ts[c][r + kh][tid + kw], a);
            out[r] = a;
        }
    };

    auto wred_atomic = [&](float v, float* addr) {
        v += __shfl_xor_sync(0xffffffffu, v, 16);
        v += __shfl_xor_sync(0xffffffffu, v, 8);
        v += __shfl_xor_sync(0xffffffffu, v, 4);
        v += __shfl_xor_sync(0xffffffffu, v, 2);
        v += __shfl_xor_sync(0xffffffffu, v, 1);
        if (lane == 0) atomicAdd(addr, v);
    };

    float dq[8][8];

#pragma unroll 1
    for (int hd = 0; hd < HEADS; hd++) {
#pragma unroll 1
        for (int half = 0; half < 2; half++) {
            int gc0 = hd * 8 + half * 4;
            stage4(gc0);
#pragma unroll
            for (int c = 0; c < 4; c++) {
                float o[8];
                dwcol(c, gc0 + c, o);
                int i = half * 4 + c;
#pragma unroll
                for (int r = 0; r < 8; r++) dq[i][r] = o[r];
            }
        }
#pragma unroll
        for (int i = 0; i < 8; i++) {
            float s = 0.f;
#pragma unroll
            for (int r = 0; r < 8; r++) s = fmaf(dq[i][r], dq[i][r], s);
            wred_atomic(s, sqb + hd * 8 + i);
        }
#pragma unroll 1
        for (int half = 0; half < 2; half++) {
            int gc0 = 64 + hd * 8 + half * 4;
            stage4(gc0);
#pragma unroll
            for (int c = 0; c < 4; c++) {
                int j = half * 4 + c;
                float dk[8];
                dwcol(c, gc0 + c, dk);
                float s = 0.f;
#pragma unroll
                for (int r = 0; r < 8; r++) s = fmaf(dk[r], dk[r], s);
                wred_atomic(s, sqb + 64 + hd * 8 + j);
#pragma unroll
                for (int i = 0; i < 8; i++) {
                    float g = 0.f;
#pragma unroll
                    for (int r = 0; r < 8; r++) g = fmaf(dq[i][r], dk[r], g);
                    wred_atomic(g, gramb + (hd * 8 + i) * 8 + j);
                }
            }
        }
    }
}

// ---------------- K2b: depthwise 3x3 on v + store ----------------
__global__ __launch_bounds__(256, 2) void k2b_v(const float* __restrict__ wd1,
                                                const float* __restrict__ wd2) {
    __shared__ float ts[4][10][258];
    __shared__ float swd[64 * 9];

    int bb = blockIdx.y;
    int br = bb & 1;
    int h0 = blockIdx.x * 8;
    int tid = threadIdx.x;
    const float* wdg = (br ? wd2 : wd1) + 128 * 9;
    for (int i = tid; i < 64 * 9; i += 256) swd[i] = wdg[i];
    if (tid < 40) {
        int c = tid / 10, r = tid - c * 10;
        ts[c][r][0] = 0.f;
        ts[c][r][257] = 0.f;
    }

    const float* pwb = g_pw + (size_t)bb * OC * Npix + (size_t)128 * Npix;
    float* vbp = g_v + (size_t)bb * D * Npix;

#pragma unroll 1
    for (int gq = 0; gq < 16; gq++) {
        int gc0 = gq * 4;
        __syncthreads();
#pragma unroll
        for (int c = 0; c < 4; c++) {
            const float* chp = pwb + (size_t)(gc0 + c) * Npix;
#pragma unroll
            for (int r = 0; r < 10; r++) {
                int gh = h0 + r - 1;
                float v = 0.f;
                if ((unsigned)gh < Himg) v = chp[gh * Wimg + tid];
                ts[c][r][1 + tid] = v;
            }
        }
        __syncthreads();
#pragma unroll
        for (int c = 0; c < 4; c++) {
            float w[9];
#pragma unroll
            for (int i = 0; i < 9; i++) w[i] = swd[(gc0 + c) * 9 + i];
            float* op = vbp + (size_t)(gc0 + c) * Npix;
#pragma unroll
            for (int r = 0; r < 8; r++) {
                float a = 0.f;
#pragma unroll
                for (int kh = 0; kh < 3; kh++)
#pragma unroll
                    for (int kw = 0; kw < 3; kw++)
                        a = fmaf(w[kh * 3 + kw], ts[c][r + kh][tid + kw], a);
                op[(h0 + r) * Wimg + tid] = a;
            }
        }
    }
}

// ---------------- K3: attn softmax + fold with w_po into M ----------------
__global__ __launch_bounds__(256) void k3_attn(const float* __restrict__ wpo1,
                                               const float* __restrict__ wpo2,
                                               const float* __restrict__ t1,
                                               const float* __restrict__ t2) {
    int bb = blockIdx.x;
    int br = bb & 1;
    __shared__ float attn[64][9];
    __shared__ float qn[64], kn[64];
    __shared__ float swpo[4096];
    int t = threadIdx.x;
    const float* wpo = br ? wpo2 : wpo1;
    for (int i = t; i < 4096; i += 256) swpo[i] = wpo[i];
    if (t < 64) {
        qn[t] = fmaxf(sqrtf(g_sq[bb * 128 + t]), 1e-12f);
        kn[t] = fmaxf(sqrtf(g_sq[bb * 128 + 64 + t]), 1e-12f);
    }
    __syncthreads();
    const float* tv = br ? t2 : t1;
    if (t < 64) {
        int hh = t >> 3;
        float tt = tv[hh];
        float s[8], m = -1e30f;
#pragma unroll
        for (int j = 0; j < 8; j++) {
            s[j] = g_gram[bb * 512 + t * 8 + j] / (qn[t] * kn[hh * 8 + j]) * tt;
            m = fmaxf(m, s[j]);
        }
        float sum = 0.f;
#pragma unroll
        for (int j = 0; j < 8; j++) { s[j] = expf(s[j] - m); sum += s[j]; }
        float inv = 1.f / sum;
#pragma unroll
        for (int j = 0; j < 8; j++) attn[t][j] = s[j] * inv;
    }
    __syncthreads();
    {
        int o = t >> 2, dg = t & 3;
#pragma unroll
        for (int dd = 0; dd < 16; dd++) {
            int d = dg * 16 + dd;
            int hd = d >> 3;
            float acc = 0.f;
#pragma unroll
            for (int ci = 0; ci < 8; ci++)
                acc = fmaf(swpo[o * 64 + hd * 8 + ci], attn[hd * 8 + ci][d & 7], acc);
            g_M[bb * 4096 + o * 64 + d] = acc;
        }
    }
}

// ---------------- K4: out = M @ v_other, occ-2, double-buffered cp.async ----------------
#define PXT 256
#define PXU 128
#define KC 8

__global__ __launch_bounds__(256, 2) void k4_out(float* __restrict__ out) {
    __shared__ float sW[64 * 64];
    __shared__ unsigned long long sX[2][KC * PXU];

    int pxt = blockIdx.x;
    int bh = blockIdx.y;
    int b = bh >> 1, half = bh & 1;
    int mi = b * 2 + half;
    int vi = b * 2 + (1 - half);
    int tid = threadIdx.x, lane = tid & 31, wp = tid >> 5;

    for (int i = tid; i < 4096; i += 256) sW[i] = g_M[mi * 4096 + i];

    const float* vbp = g_v + (size_t)vi * D * Npix + pxt * PXT;
    float* outb = out + ((size_t)(b * 128 + half * 64)) * Npix + pxt * PXT;

    auto stage = [&](int kc0, int buf) {
        unsigned int dst = smem_u32(&sX[buf][0]);
#pragma unroll
        for (int t = 0; t < 4; t++) {
            int i = tid + t * 256;
            int r = i >> 7, c = i & 127;
            cpa8(dst + i * 8, vbp + (size_t)(kc0 + r) * Npix + c * 2);
        }
        cpa_commit();
    };

    unsigned long long acc[8][4];
#pragma unroll
    for (int r = 0; r < 8; r++)
#pragma unroll
        for (int j = 0; j < 4; j++) acc[r][j] = 0ull;

    stage(0, 0);
    int cur = 0;
#pragma unroll 1
    for (int rr = 0; rr < 8; rr++) {
        if (rr < 7) {
            stage((rr + 1) * KC, cur ^ 1);
            asm volatile("cp.async.wait_group 1;");
        } else {
            asm volatile("cp.async.wait_group 0;");
        }
        __syncthreads();
#pragma unroll
        for (int k = 0; k < KC; k++) {
            unsigned long long xv[4];
#pragma unroll
            for (int j = 0; j < 4; j++) xv[j] = sX[cur][k * PXU + lane + 32 * j];
#pragma unroll
            for (int r = 0; r < 8; r++) {
                float wv = sW[(wp * 8 + r) * 64 + rr * KC + k];
                unsigned long long w2 = pack2(wv, wv);
#pragma unroll
                for (int j = 0; j < 4; j++) acc[r][j] = ffma2(w2, xv[j], acc[r][j]);
            }
        }
        cur ^= 1;
        __syncthreads();
    }
#pragma unroll
    for (int r = 0; r < 8; r++) {
        float* orow = outb + (size_t)(wp * 8 + r) * Npix;
#pragma unroll
        for (int j = 0; j < 4; j++)
            *(unsigned long long*)(orow + (lane + 32 * j) * 2) = acc[r][j];
    }
}

extern "C" void kernel_launch(void* const* d_in, const int* in_sizes, int n_in,
                              void* d_out, int out_size) {
    const float* x   = (const float*)d_in[0];
    const float* wq1 = (const float*)d_in[1];
    const float* wq2 = (const float*)d_in[2];
    const float* wd1 = (const float*)d_in[3];
    const float* wd2 = (const float*)d_in[4];
    const float* wp1 = (const float*)d_in[5];
    const float* wp2 = (const float*)d_in[6];
    const float* t1  = (const float*)d_in[7];
    const float* t2  = (const float*)d_in[8];
    float* out = (float*)d_out;

    // k1 must be launch index 3 (ncu capture slot)
    padA_zero_sq<<<4, 256>>>();
    padB_zero_gram<<<16, 256>>>();
    padC_noop<<<1, 32>>>();
    k1_wmma<<<dim3(768, 8), 256>>>(x, wq1, wq2);
    k2a_qk<<<dim3(32, 8), 256>>>(wd1, wd2);
    k2b_v<<<dim3(32, 8), 256>>>(wd1, wd2);
    k3_attn<<<8, 256>>>(wp1, wp2, t1, t2);
    k4_out<<<dim3(256, 8), 256>>>(out);
}

// round 8
// speedup vs baseline: 1.6451x; 1.0224x over previous
#include <cuda_runtime.h>
#include <math.h>
#include <stdint.h>
#include <mma.h>

using namespace nvcuda;

#define BATCH 4
#define D 64
#define Himg 256
#define Wimg 256
#define Npix 65536
#define OC 192
#define HEADS 8

__device__ float g_pw[(size_t)8 * OC * Npix];   // pw conv output, [b*2+br][192][N]
__device__ float g_v[(size_t)8 * D * Npix];     // v after dw,   [b*2+br][64][N]
__device__ float g_sq[8 * 128];                 // sumsq q(64)+k(64) per (b,br)
__device__ float g_gram[8 * 64 * 8];            // Gram [c][j] per (b,br)
__device__ float g_M[8 * 64 * 64];              // folded (w_po @ attn) per (b,br)

__device__ __forceinline__ void cpa16(unsigned int dst, const void* src) {
    asm volatile("cp.async.ca.shared.global [%0], [%1], 16;" :: "r"(dst), "l"(src));
}
__device__ __forceinline__ void cpa_commit() {
    asm volatile("cp.async.commit_group;");
}
__device__ __forceinline__ unsigned int smem_u32(const void* p) {
    return (unsigned int)__cvta_generic_to_shared(p);
}

// ---------------- pads ----------------
__global__ void padA_zero_sq() {
    int i = blockIdx.x * blockDim.x + threadIdx.x;
    if (i < 8 * 128) g_sq[i] = 0.f;
}
__global__ void padB_zero_gram() {
    int i = blockIdx.x * blockDim.x + threadIdx.x;
    if (i < 8 * 64 * 8) g_gram[i] = 0.f;
}

// ---------------- K1: pointwise conv via wmma tf32, occ-2 ----------------
#define K1_LDW 72
#define K1_LDX 264

__global__ __launch_bounds__(256, 2) void k1_wmma(const float* __restrict__ x,
                                                  const float* __restrict__ wq1,
                                                  const float* __restrict__ wq2) {
    __shared__ float sW[64 * K1_LDW];
    __shared__ float sX[2][8 * K1_LDX];

    int bx = blockIdx.x;
    int oct = bx % 3, pxt = bx / 3;
    int bb = blockIdx.y, b = bb >> 1, br = bb & 1;
    const float* wq = br ? wq2 : wq1;
    int tid = threadIdx.x;
    int wid = tid >> 5;
    int ocw = wid >> 2;
    int pxw = wid & 3;
    int px0 = pxt * 256;

    for (int i = tid; i < 4096; i += 256) {
        int row = i >> 6, c = i & 63;
        sW[row * K1_LDW + c] = wq[oct * 4096 + i];
    }

    const float* xb = x + ((size_t)(b * 128 + br * 64)) * Npix + px0;
    float* pwb = g_pw + (size_t)bb * OC * Npix + (size_t)(oct * 64) * Npix + px0;

    auto stage = [&](int kc0, int buf) {
        unsigned int dstb = smem_u32(&sX[buf][0]);
#pragma unroll
        for (int t = 0; t < 2; t++) {
            int ch = tid + t * 256;
            int r = ch >> 6, c16 = ch & 63;
            cpa16(dstb + (r * K1_LDX + c16 * 4) * 4,
                  xb + (size_t)(kc0 + r) * Npix + c16 * 4);
        }
        cpa_commit();
    };

    wmma::fragment<wmma::accumulator, 16, 16, 8, float> acc[2][4];
#pragma unroll
    for (int co = 0; co < 2; co++)
#pragma unroll
        for (int pb = 0; pb < 4; pb++) wmma::fill_fragment(acc[co][pb], 0.f);

    stage(0, 0);
    int cur = 0;
    __syncthreads();
#pragma unroll 1
    for (int rr = 0; rr < 8; rr++) {
        if (rr < 7) {
            stage((rr + 1) * 8, cur ^ 1);
            asm volatile("cp.async.wait_group 1;");
        } else {
            asm volatile("cp.async.wait_group 0;");
        }
        __syncthreads();

        wmma::fragment<wmma::matrix_a, 16, 16, 8, wmma::precision::tf32, wmma::row_major> af[2];
#pragma unroll
        for (int co = 0; co < 2; co++) {
            wmma::load_matrix_sync(af[co], &sW[(ocw * 32 + co * 16) * K1_LDW + rr * 8], K1_LDW);
#pragma unroll
            for (int e = 0; e < af[co].num_elements; e++)
                af[co].x[e] = wmma::__float_to_tf32(af[co].x[e]);
        }
#pragma unroll
        for (int pb = 0; pb < 4; pb++) {
            wmma::fragment<wmma::matrix_b, 16, 16, 8, wmma::precision::tf32, wmma::row_major> bf;
            wmma::load_matrix_sync(bf, &sX[cur][pxw * 64 + pb * 16], K1_LDX);
#pragma unroll
            for (int e = 0; e < bf.num_elements; e++)
                bf.x[e] = wmma::__float_to_tf32(bf.x[e]);
#pragma unroll
            for (int co = 0; co < 2; co++)
                wmma::mma_sync(acc[co][pb], af[co], bf, acc[co][pb]);
        }
        cur ^= 1;
        __syncthreads();
    }

#pragma unroll
    for (int co = 0; co < 2; co++)
#pragma unroll
        for (int pb = 0; pb < 4; pb++)
            wmma::store_matrix_sync(
                pwb + (size_t)(ocw * 32 + co * 16) * Npix + pxw * 64 + pb * 16,
                acc[co][pb], Npix, wmma::mem_row_major);
}

// ---------------- K2a: depthwise 3x3 on q,k + Gram/sumsq (UNCHANGED, being profiled) ----------------
__global__ __launch_bounds__(256) void k2a_qk(const float* __restrict__ wd1,
                                              const float* __restrict__ wd2) {
    __shared__ float ts[4][10][258];
    __shared__ float swd[128 * 9];

    int bb = blockIdx.y;
    int br = bb & 1;
    int h0 = blockIdx.x * 8;
    int tid = threadIdx.x;
    int lane = tid & 31;
    const float* wdg = br ? wd2 : wd1;
    for (int i = tid; i < 128 * 9; i += 256) swd[i] = wdg[i];
    if (tid < 40) {
        int c = tid / 10, r = tid - c * 10;
        ts[c][r][0] = 0.f;
        ts[c][r][257] = 0.f;
    }

    const float* pwb = g_pw + (size_t)bb * OC * Npix;
    float* gramb = g_gram + bb * 512;
    float* sqb = g_sq + bb * 128;

    auto stage4 = [&](int gc0) {
        __syncthreads();
#pragma unroll
        for (int c = 0; c < 4; c++) {
            const float* chp = pwb + (size_t)(gc0 + c) * Npix;
#pragma unroll
            for (int r = 0; r < 10; r++) {
                int gh = h0 + r - 1;
                float v = 0.f;
                if ((unsigned)gh < Himg) v = chp[gh * Wimg + tid];
                ts[c][r][1 + tid] = v;
            }
        }
        __syncthreads();
    };

    auto dwcol = [&](int c, int gc, float out[8]) {
        float w[9];
#pragma unroll
        for (int i = 0; i < 9; i++) w[i] = swd[gc * 9 + i];
#pragma unroll
        for (int r = 0; r < 8; r++) {
            float a = 0.f;
#pragma unroll
            for (int kh = 0; kh < 3; kh++)
#pragma unroll
                for (int kw = 0; kw < 3; kw++)
                    a = fmaf(w[kh * 3 + kw], ts[c][r + kh][tid + kw], a);
            out[r] = a;
        }
    };

    auto wred_atomic = [&](float v, float* addr) {
        v += __shfl_xor_sync(0xffffffffu, v, 16);
        v += __shfl_xor_sync(0xffffffffu, v, 8);
        v += __shfl_xor_sync(0xffffffffu, v, 4);
        v += __shfl_xor_sync(0xffffffffu, v, 2);
        v += __shfl_xor_sync(0xffffffffu, v, 1);
        if (lane == 0) atomicAdd(addr, v);
    };

    float dq[8][8];

#pragma unroll 1
    for (int hd = 0; hd < HEADS; hd++) {
#pragma unroll 1
        for (int half = 0; half < 2; half++) {
            int gc0 = hd * 8 + half * 4;
            stage4(gc0);
#pragma unroll
            for (int c = 0; c < 4; c++) {
                float o[8];
                dwcol(c, gc0 + c, o);
                int i = half * 4 + c;
#pragma unroll
                for (int r = 0; r < 8; r++) dq[i][r] = o[r];
            }
        }
#pragma unroll
        for (int i = 0; i < 8; i++) {
            float s = 0.f;
#pragma unroll
            for (int r = 0; r < 8; r++) s = fmaf(dq[i][r], dq[i][r], s);
            wred_atomic(s, sqb + hd * 8 + i);
        }
#pragma unroll 1
        for (int half = 0; half < 2; half++) {
            int gc0 = 64 + hd * 8 + half * 4;
            stage4(gc0);
#pragma unroll
            for (int c = 0; c < 4; c++) {
                int j = half * 4 + c;
                float dk[8];
                dwcol(c, gc0 + c, dk);
                float s = 0.f;
#pragma unroll
                for (int r = 0; r < 8; r++) s = fmaf(dk[r], dk[r], s);
                wred_atomic(s, sqb + 64 + hd * 8 + j);
#pragma unroll
                for (int i = 0; i < 8; i++) {
                    float g = 0.f;
#pragma unroll
                    for (int r = 0; r < 8; r++) g = fmaf(dq[i][r], dk[r], g);
                    wred_atomic(g, gramb + (hd * 8 + i) * 8 + j);
                }
            }
        }
    }
}

// ---------------- K2b: depthwise 3x3 on v + store ----------------
__global__ __launch_bounds__(256, 2) void k2b_v(const float* __restrict__ wd1,
                                                const float* __restrict__ wd2) {
    __shared__ float ts[4][10][258];
    __shared__ float swd[64 * 9];

    int bb = blockIdx.y;
    int br = bb & 1;
    int h0 = blockIdx.x * 8;
    int tid = threadIdx.x;
    const float* wdg = (br ? wd2 : wd1) + 128 * 9;
    for (int i = tid; i < 64 * 9; i += 256) swd[i] = wdg[i];
    if (tid < 40) {
        int c = tid / 10, r = tid - c * 10;
        ts[c][r][0] = 0.f;
        ts[c][r][257] = 0.f;
    }

    const float* pwb = g_pw + (size_t)bb * OC * Npix + (size_t)128 * Npix;
    float* vbp = g_v + (size_t)bb * D * Npix;

#pragma unroll 1
    for (int gq = 0; gq < 16; gq++) {
        int gc0 = gq * 4;
        __syncthreads();
#pragma unroll
        for (int c = 0; c < 4; c++) {
            const float* chp = pwb + (size_t)(gc0 + c) * Npix;
#pragma unroll
            for (int r = 0; r < 10; r++) {
                int gh = h0 + r - 1;
                float v = 0.f;
                if ((unsigned)gh < Himg) v = chp[gh * Wimg + tid];
                ts[c][r][1 + tid] = v;
            }
        }
        __syncthreads();
#pragma unroll
        for (int c = 0; c < 4; c++) {
            float w[9];
#pragma unroll
            for (int i = 0; i < 9; i++) w[i] = swd[(gc0 + c) * 9 + i];
            float* op = vbp + (size_t)(gc0 + c) * Npix;
#pragma unroll
            for (int r = 0; r < 8; r++) {
                float a = 0.f;
#pragma unroll
                for (int kh = 0; kh < 3; kh++)
#pragma unroll
                    for (int kw = 0; kw < 3; kw++)
                        a = fmaf(w[kh * 3 + kw], ts[c][r + kh][tid + kw], a);
                op[(h0 + r) * Wimg + tid] = a;
            }
        }
    }
}

// ---------------- K3: attn softmax + fold with w_po into M ----------------
__global__ __launch_bounds__(256) void k3_attn(const float* __restrict__ wpo1,
                                               const float* __restrict__ wpo2,
                                               const float* __restrict__ t1,
                                               const float* __restrict__ t2) {
    int bb = blockIdx.x;
    int br = bb & 1;
    __shared__ float attn[64][9];
    __shared__ float qn[64], kn[64];
    __shared__ float swpo[4096];
    int t = threadIdx.x;
    const float* wpo = br ? wpo2 : wpo1;
    for (int i = t; i < 4096; i += 256) swpo[i] = wpo[i];
    if (t < 64) {
        qn[t] = fmaxf(sqrtf(g_sq[bb * 128 + t]), 1e-12f);
        kn[t] = fmaxf(sqrtf(g_sq[bb * 128 + 64 + t]), 1e-12f);
    }
    __syncthreads();
    const float* tv = br ? t2 : t1;
    if (t < 64) {
        int hh = t >> 3;
        float tt = tv[hh];
        float s[8], m = -1e30f;
#pragma unroll
        for (int j = 0; j < 8; j++) {
            s[j] = g_gram[bb * 512 + t * 8 + j] / (qn[t] * kn[hh * 8 + j]) * tt;
            m = fmaxf(m, s[j]);
        }
        float sum = 0.f;
#pragma unroll
        for (int j = 0; j < 8; j++) { s[j] = expf(s[j] - m); sum += s[j]; }
        float inv = 1.f / sum;
#pragma unroll
        for (int j = 0; j < 8; j++) attn[t][j] = s[j] * inv;
    }
    __syncthreads();
    {
        int o = t >> 2, dg = t & 3;
#pragma unroll
        for (int dd = 0; dd < 16; dd++) {
            int d = dg * 16 + dd;
            int hd = d >> 3;
            float acc = 0.f;
#pragma unroll
            for (int ci = 0; ci < 8; ci++)
                acc = fmaf(swpo[o * 64 + hd * 8 + ci], attn[hd * 8 + ci][d & 7], acc);
            g_M[bb * 4096 + o * 64 + d] = acc;
        }
    }
}

// ---------------- K4: out = M @ v_other via wmma tf32 ----------------
__global__ __launch_bounds__(256, 2) void k4_wmma(float* __restrict__ out) {
    __shared__ float sW[64 * K1_LDW];
    __shared__ float sX[2][8 * K1_LDX];

    int pxt = blockIdx.x;
    int bh = blockIdx.y;
    int b = bh >> 1, half = bh & 1;
    int mi = b * 2 + half;
    int vi = b * 2 + (1 - half);
    int tid = threadIdx.x;
    int wid = tid >> 5;
    int ocw = wid >> 2;
    int pxw = wid & 3;
    int px0 = pxt * 256;

    for (int i = tid; i < 4096; i += 256) {
        int row = i >> 6, c = i & 63;
        sW[row * K1_LDW + c] = g_M[mi * 4096 + i];
    }

    const float* vbp = g_v + (size_t)vi * D * Npix + px0;
    float* outb = out + ((size_t)(b * 128 + half * 64)) * Npix + px0;

    auto stage = [&](int kc0, int buf) {
        unsigned int dstb = smem_u32(&sX[buf][0]);
#pragma unroll
        for (int t = 0; t < 2; t++) {
            int ch = tid + t * 256;
            int r = ch >> 6, c16 = ch & 63;
            cpa16(dstb + (r * K1_LDX + c16 * 4) * 4,
                  vbp + (size_t)(kc0 + r) * Npix + c16 * 4);
        }
        cpa_commit();
    };

    wmma::fragment<wmma::accumulator, 16, 16, 8, float> acc[2][4];
#pragma unroll
    for (int co = 0; co < 2; co++)
#pragma unroll
        for (int pb = 0; pb < 4; pb++) wmma::fill_fragment(acc[co][pb], 0.f);

    stage(0, 0);
    int cur = 0;
    __syncthreads();
#pragma unroll 1
    for (int rr = 0; rr < 8; rr++) {
        if (rr < 7) {
            stage((rr + 1) * 8, cur ^ 1);
            asm volatile("cp.async.wait_group 1;");
        } else {
            asm volatile("cp.async.wait_group 0;");
        }
        __syncthreads();

        wmma::fragment<wmma::matrix_a, 16, 16, 8, wmma::precision::tf32, wmma::row_major> af[2];
#pragma unroll
        for (int co = 0; co < 2; co++) {
            wmma::load_matrix_sync(af[co], &sW[(ocw * 32 + co * 16) * K1_LDW + rr * 8], K1_LDW);
#pragma unroll
            for (int e = 0; e < af[co].num_elements; e++)
                af[co].x[e] = wmma::__float_to_tf32(af[co].x[e]);
        }
#pragma unroll
        for (int pb = 0; pb < 4; pb++) {
            wmma::fragment<wmma::matrix_b, 16, 16, 8, wmma::precision::tf32, wmma::row_major> bf;
            wmma::load_matrix_sync(bf, &sX[cur][pxw * 64 + pb * 16], K1_LDX);
#pragma unroll
            for (int e = 0; e < bf.num_elements; e++)
                bf.x[e] = wmma::__float_to_tf32(bf.x[e]);
#pragma unroll
            for (int co = 0; co < 2; co++)
                wmma::mma_sync(acc[co][pb], af[co], bf, acc[co][pb]);
        }
        cur ^= 1;
        __syncthreads();
    }

#pragma unroll
    for (int co = 0; co < 2; co++)
#pragma unroll
        for (int pb = 0; pb < 4; pb++)
            wmma::store_matrix_sync(
                outb + (size_t)(ocw * 32 + co * 16) * Npix + pxw * 64 + pb * 16,
                acc[co][pb], Npix, wmma::mem_row_major);
}

extern "C" void kernel_launch(void* const* d_in, const int* in_sizes, int n_in,
                              void* d_out, int out_size) {
    const float* x   = (const float*)d_in[0];
    const float* wq1 = (const float*)d_in[1];
    const float* wq2 = (const float*)d_in[2];
    const float* wd1 = (const float*)d_in[3];
    const float* wd2 = (const float*)d_in[4];
    const float* wp1 = (const float*)d_in[5];
    const float* wp2 = (const float*)d_in[6];
    const float* t1  = (const float*)d_in[7];
    const float* t2  = (const float*)d_in[8];
    float* out = (float*)d_out;

    // k2a must be launch index 3 (ncu capture slot)
    padA_zero_sq<<<4, 256>>>();
    padB_zero_gram<<<16, 256>>>();
    k1_wmma<<<dim3(768, 8), 256>>>(x, wq1, wq2);
    k2a_qk<<<dim3(32, 8), 256>>>(wd1, wd2);
    k2b_v<<<dim3(32, 8), 256>>>(wd1, wd2);
    k3_attn<<<8, 256>>>(wp1, wp2, t1, t2);
    k4_wmma<<<dim3(256, 8), 256>>>(out);
}